// round 7
// baseline (speedup 1.0000x reference)
#include <cuda_runtime.h>
#include <cuda_fp16.h>
#include <cstdint>

// ---------------------------------------------------------------------------
// Problem constants
// ---------------------------------------------------------------------------
#define SEQ   2048
#define DM    4096
#define NH    32
#define NKV   8
#define HD    128
#define KVD   (NKV * HD)   // 1024

typedef __half h16;

// ---------------------------------------------------------------------------
// Device-global scratch (allocation-free rule)
// ---------------------------------------------------------------------------
__device__ float g_xq[SEQ * DM];
__device__ float g_xk[SEQ * KVD];
__device__ float g_xv[SEQ * KVD];
__device__ float g_sc[(size_t)NH * SEQ * SEQ];     // fp32 scores
__device__ float g_att[SEQ * DM];

// fp16 operands
__device__ __align__(16) h16 g_xh [SEQ * DM];                    // x plain fp16 (v-proj)
__device__ __align__(16) h16 g_qh [SEQ * DM],  g_ql [SEQ * DM];  // q split (QK)
__device__ __align__(16) h16 g_kh [SEQ * KVD], g_kl [SEQ * KVD]; // k split (QK)
__device__ __align__(16) h16 g_vth[NKV * HD * SEQ];              // V^T plain
__device__ __align__(16) h16 g_ath[SEQ * DM];                    // att plain
__device__ __align__(16) h16 g_ph [(size_t)NH * SEQ * SEQ];      // probs plain
__device__ __align__(16) h16 g_wvh[KVD * DM];                    // v weights fp16
__device__ __align__(16) h16 g_woh[DM * DM];                     // o weights fp16

// int8 digit operands for q/k projections
__device__ __align__(16) int8_t g_xd0[SEQ * DM];
__device__ __align__(16) int8_t g_xd1[SEQ * DM];
__device__ __align__(16) int8_t g_xd2[SEQ * DM];
__device__ float g_sa[SEQ];                                      // per-row act scale
__device__ __align__(16) int8_t g_nibq[DM * DM];                 // wq nibbles planar
__device__ __align__(16) int8_t g_nibk[KVD * DM];                // wk nibbles planar

// canonical int8 packed weights
__device__ int8_t g_wq8[DM * DM / 2];
__device__ int8_t g_wk8[KVD * DM / 2];
__device__ int8_t g_wv8[KVD * DM / 2];
__device__ int8_t g_wo8[DM * DM / 2];
__device__ int    g_mode;

// ---------------------------------------------------------------------------
// PTX helpers (base sm_103 ISA: cp.async / ldmatrix / mma.sync)
// ---------------------------------------------------------------------------
__device__ __forceinline__ uint32_t smem_u32(const void* p) {
    uint32_t a;
    asm("{ .reg .u64 t; cvta.to.shared.u64 t, %1; cvt.u32.u64 %0, t; }" : "=r"(a) : "l"(p));
    return a;
}
__device__ __forceinline__ void cp16(uint32_t dst, const void* src) {
    asm volatile("cp.async.cg.shared.global [%0], [%1], 16;" :: "r"(dst), "l"(src) : "memory");
}
__device__ __forceinline__ void cp4(uint32_t dst, const void* src) {
    asm volatile("cp.async.ca.shared.global [%0], [%1], 4;" :: "r"(dst), "l"(src) : "memory");
}
__device__ __forceinline__ void cp_commit() {
    asm volatile("cp.async.commit_group;" ::: "memory");
}
template <int N>
__device__ __forceinline__ void cp_wait() {
    asm volatile("cp.async.wait_group %0;" :: "n"(N) : "memory");
}
__device__ __forceinline__ void ldm_x4(uint32_t* r, uint32_t addr) {
    asm volatile("ldmatrix.sync.aligned.m8n8.x4.shared.b16 {%0,%1,%2,%3}, [%4];"
                 : "=r"(r[0]), "=r"(r[1]), "=r"(r[2]), "=r"(r[3]) : "r"(addr));
}
// fp16 MMA, fp32 accumulate
__device__ __forceinline__ void mma_f32(float* d, const uint32_t* a,
                                        uint32_t b0, uint32_t b1) {
    asm volatile(
        "mma.sync.aligned.m16n8k16.row.col.f32.f16.f16.f32 "
        "{%0,%1,%2,%3}, {%4,%5,%6,%7}, {%8,%9}, {%0,%1,%2,%3};"
        : "+f"(d[0]), "+f"(d[1]), "+f"(d[2]), "+f"(d[3])
        : "r"(a[0]), "r"(a[1]), "r"(a[2]), "r"(a[3]), "r"(b0), "r"(b1));
}
// fp16 MMA, fp16 accumulate (small cross terms)
__device__ __forceinline__ void mma_f16(uint32_t* d, const uint32_t* a,
                                        uint32_t b0, uint32_t b1) {
    asm volatile(
        "mma.sync.aligned.m16n8k16.row.col.f16.f16.f16.f16 "
        "{%0,%1}, {%2,%3,%4,%5}, {%6,%7}, {%0,%1};"
        : "+r"(d[0]), "+r"(d[1])
        : "r"(a[0]), "r"(a[1]), "r"(a[2]), "r"(a[3]), "r"(b0), "r"(b1));
}
// int8 MMA k32, s32 accumulate
__device__ __forceinline__ void mma_s8(int* d, const uint32_t* a,
                                       uint32_t b0, uint32_t b1) {
    asm volatile(
        "mma.sync.aligned.m16n8k32.row.col.s32.s8.s8.s32 "
        "{%0,%1,%2,%3}, {%4,%5,%6,%7}, {%8,%9}, {%0,%1,%2,%3};"
        : "+r"(d[0]), "+r"(d[1]), "+r"(d[2]), "+r"(d[3])
        : "r"(a[0]), "r"(a[1]), "r"(a[2]), "r"(a[3]), "r"(b0), "r"(b1));
}

// Permuted conflict-free smem layout: atom = 8 rows x 16B chunk, 128B blocks.
// For fp16 tiles: 128 rows x 32 b16 (kc = k16-byte chunk index 0..3).
// For int8 tiles: 128 rows x 64 bytes (kc = 16-byte chunk 0..3). Same math.
__device__ __forceinline__ uint32_t tile_off(int row, int kc) {
    return (uint32_t)((((row >> 3) * 4 + kc) << 7) + ((row & 7) << 4));
}

// ---------------------------------------------------------------------------
// Probe + repack (dtype-robust weight ingestion)
// ---------------------------------------------------------------------------
__global__ void probe_mode(const int* __restrict__ w)
{
    if (threadIdx.x == 0 && blockIdx.x == 0) {
        int ok = 0;
        for (int i = 0; i < 256; i++) {
            const int v = w[i];
            if (v >= -128 && v <= 127) ok++;
        }
        g_mode = (ok >= 250) ? 1 : 0;
    }
}
__global__ __launch_bounds__(256) void repack_w(
    const void* __restrict__ in, int8_t* __restrict__ out, long n)
{
    const int mode = g_mode;
    const long stride = (long)gridDim.x * blockDim.x;
    for (long i = (long)blockIdx.x * blockDim.x + threadIdx.x; i < n; i += stride) {
        if (mode) out[i] = (int8_t)((const int*)in)[i];
        else      out[i] = ((const int8_t*)in)[i];
    }
}

// Unpack Q4_0 nibbles to planar int8 (no scale).
__global__ __launch_bounds__(256) void unpack_nib(
    const int8_t* __restrict__ w8, int8_t* __restrict__ nib, long n)
{
    const long stride = (long)gridDim.x * blockDim.x;
    for (long f = (long)blockIdx.x * blockDim.x + threadIdx.x; f < n; f += stride) {
        const long r = f >> 7;
        const int  q = (int)(f & 127);
        const int8_t b = w8[r * 64 + (q & 63)];
        nib[f] = (q < 64) ? (int8_t)(b >> 4) : (int8_t)(((int8_t)(b << 4)) >> 4);
    }
}

// Dequant Q4_0 -> plain fp16 (value path weights)
__global__ __launch_bounds__(256) void dequant_plain_w(
    const int8_t* __restrict__ w8, const float* __restrict__ sc,
    h16* __restrict__ wh, long n)
{
    const long stride = (long)gridDim.x * blockDim.x;
    for (long f = (long)blockIdx.x * blockDim.x + threadIdx.x; f < n; f += stride) {
        const long r = f >> 7;
        const int  q = (int)(f & 127);
        const int8_t b = w8[r * 64 + (q & 63)];
        const int nib = (q < 64) ? (b >> 4) : (((int8_t)(b << 4)) >> 4);
        wh[f] = __float2half((float)nib * sc[f >> 6]);
    }
}

// fp32 -> fp16 convert
__global__ __launch_bounds__(256) void cvt_f32h(
    const float* __restrict__ src, h16* __restrict__ dst, long n)
{
    const long stride = (long)gridDim.x * blockDim.x;
    for (long i = (long)blockIdx.x * blockDim.x + threadIdx.x; i < n; i += stride)
        dst[i] = __float2half(src[i]);
}

// ---------------------------------------------------------------------------
// Quantize x per-row to 3 int8 digits: x ~= sa * (d0 + d1/128 + d2/16384)
// One block (256 threads) per row.
// ---------------------------------------------------------------------------
__global__ __launch_bounds__(256) void quant_x3(
    const float* __restrict__ x, int8_t* __restrict__ d0,
    int8_t* __restrict__ d1, int8_t* __restrict__ d2, float* __restrict__ sa)
{
    const int row = blockIdx.x;
    const float* p = x + (size_t)row * DM;
    const int tid = threadIdx.x;
    __shared__ float red[8];

    float mx = 0.0f;
    for (int k = tid; k < DM; k += 256) mx = fmaxf(mx, fabsf(p[k]));
#pragma unroll
    for (int o = 16; o > 0; o >>= 1) mx = fmaxf(mx, __shfl_xor_sync(0xffffffffu, mx, o));
    if ((tid & 31) == 0) red[tid >> 5] = mx;
    __syncthreads();
    mx = red[0];
#pragma unroll
    for (int i = 1; i < 8; i++) mx = fmaxf(mx, red[i]);

    const float s   = (mx > 0.0f) ? (mx / 127.0f) : 1.0f;
    const float inv = 1.0f / s;
    if (tid == 0) sa[row] = s;

    for (int k = tid; k < DM; k += 256) {
        const float v  = p[k] * inv;
        const float f0 = rintf(v);
        const float r0 = (v - f0) * 128.0f;
        const float f1 = rintf(r0);
        const float f2 = rintf((r0 - f1) * 128.0f);
        const size_t o = (size_t)row * DM + k;
        d0[o] = (int8_t)(int)f0;
        d1[o] = (int8_t)(int)f1;
        d2[o] = (int8_t)(int)f2;
    }
}

// ---------------------------------------------------------------------------
// RoPE (rotate-half) + optional scale + fp16 split.  x laid out [S, nh, HD].
// ---------------------------------------------------------------------------
__global__ __launch_bounds__(256) void rope_split(
    const float* __restrict__ x, const float* __restrict__ cosb,
    const float* __restrict__ sinb, h16* __restrict__ oh, h16* __restrict__ ol,
    int nheads, float scale)
{
    const long total = (long)SEQ * nheads * 64;
    long idx = (long)blockIdx.x * blockDim.x + threadIdx.x;
    if (idx >= total) return;
    const int d = (int)(idx & 63);
    const int h = (int)((idx >> 6) % nheads);
    const int s = (int)(idx / ((long)64 * nheads));
    const size_t base = (size_t)s * nheads * HD + h * HD + d;
    const float c  = cosb[s * 64 + d];
    const float sn = sinb[s * 64 + d];
    const float lo = x[base];
    const float hi = x[base + 64];
    const float r0 = (lo * c - hi * sn) * scale;
    const float r1 = (hi * c + lo * sn) * scale;
    h16 h0 = __float2half(r0);
    h16 h1 = __float2half(r1);
    oh[base]      = h0;
    ol[base]      = __float2half(r0 - __half2float(h0));
    oh[base + 64] = h1;
    ol[base + 64] = __float2half(r1 - __half2float(h1));
}

// ---------------------------------------------------------------------------
// Transpose V to plain fp16: vt[kv][d][s] = xv[s][kv*HD + d]
// ---------------------------------------------------------------------------
__global__ __launch_bounds__(256) void vtrans_h(
    const float* __restrict__ xv, h16* __restrict__ vt)
{
    const long total = (long)NKV * HD * SEQ;
    long idx = (long)blockIdx.x * blockDim.x + threadIdx.x;
    if (idx >= total) return;
    const int s  = (int)(idx % SEQ);
    const int d  = (int)((idx / SEQ) % HD);
    const int kv = (int)(idx / ((long)SEQ * HD));
    vt[idx] = __float2half(xv[(size_t)s * KVD + kv * HD + d]);
}

// ---------------------------------------------------------------------------
// Causal row softmax: fp32 scores -> plain fp16 probs, zero-filled to the
// next 128 boundary.
// ---------------------------------------------------------------------------
__global__ __launch_bounds__(128) void softmax_h(
    const float* __restrict__ sc, h16* __restrict__ ph)
{
    const int row = blockIdx.x;          // h*SEQ + q
    const int q   = row & (SEQ - 1);
    const float* p = sc + (size_t)row * SEQ;
    h16* oh = ph + (size_t)row * SEQ;
    const int len  = q + 1;
    const int zend = ((q >> 7) + 1) << 7;
    const int tid  = threadIdx.x;

    __shared__ float red[4];

    float m = -1e30f;
    for (int k = tid; k < len; k += 128) m = fmaxf(m, p[k]);
#pragma unroll
    for (int o = 16; o > 0; o >>= 1) m = fmaxf(m, __shfl_xor_sync(0xffffffffu, m, o));
    if ((tid & 31) == 0) red[tid >> 5] = m;
    __syncthreads();
    m = fmaxf(fmaxf(red[0], red[1]), fmaxf(red[2], red[3]));
    __syncthreads();

    float sum = 0.0f;
    for (int k = tid; k < len; k += 128) sum += __expf(p[k] - m);
#pragma unroll
    for (int o = 16; o > 0; o >>= 1) sum += __shfl_xor_sync(0xffffffffu, sum, o);
    if ((tid & 31) == 0) red[tid >> 5] = sum;
    __syncthreads();
    sum = red[0] + red[1] + red[2] + red[3];

    const float inv = 1.0f / sum;
    for (int k = tid; k < len; k += 128)
        oh[k] = __float2half(__expf(p[k] - m) * inv);
    const h16 z = __float2half(0.0f);
    for (int k = len + tid; k < zend; k += 128) oh[k] = z;
}

// ---------------------------------------------------------------------------
// GEMM_I8: projection GEMM with exact int4 weights + 3-digit int8 activations.
//   C[m][n] = sa[m] * sum_g s[n][g] * sum_{k in g} (d0+d1/128+d2/16384)[m,k]*nib[n,k]
// CTA 128x128, BK=64 (= one scale group), 3-stage cp.async, 256 threads,
// 8 warps 4x2 (warp tile 32x64). IMMA m16n8k32, integer accs drained per group.
// ---------------------------------------------------------------------------
#define I8_TILE   8192                       // 128 x 64 int8
#define I8_STAGE  (4 * I8_TILE)              // d0, d1, d2, nib : 32 KB
#define I8_SMEM   (3 * I8_STAGE + 3 * 512)   // + per-stage scale row

__global__ __launch_bounds__(256, 1) void gemm_i8(
    const int8_t* __restrict__ Xd0, const int8_t* __restrict__ Xd1,
    const int8_t* __restrict__ Xd2, const int8_t* __restrict__ Nib,
    const float* __restrict__ Sc, const float* __restrict__ Sa,
    float* __restrict__ C, int K, int ldc)
{
    const int m0 = blockIdx.y * 128;
    const int n0 = blockIdx.x * 128;

    extern __shared__ char smem[];
    const uint32_t sb = smem_u32(smem);
    const uint32_t ssc = sb + 3 * I8_STAGE;      // scale rows
    const int tid  = threadIdx.x;
    const int wid  = tid >> 5;
    const int lane = tid & 31;

    const int NC = K >> 6;
    const int KG = K >> 6;                        // scale groups per row

    const int wm = (wid & 3) * 32;
    const int wn = (wid >> 2) * 64;

    float accf[2][8][4];
#pragma unroll
    for (int i = 0; i < 2; i++)
#pragma unroll
        for (int j = 0; j < 8; j++)
#pragma unroll
            for (int v = 0; v < 4; v++) accf[i][j][v] = 0.0f;

    // loader: 4 planes x 64 threads; each thread 2 rows x 4 chunks
    const int plane = tid >> 6;
    const int lj    = tid & 63;
    auto load_stage = [&](int c) {
        const int k0 = c << 6;
        const uint32_t st = sb + (uint32_t)(c % 3) * I8_STAGE + plane * I8_TILE;
        const int8_t* src;
        if      (plane == 0) src = Xd0 + (size_t)(m0) * K + k0;
        else if (plane == 1) src = Xd1 + (size_t)(m0) * K + k0;
        else if (plane == 2) src = Xd2 + (size_t)(m0) * K + k0;
        else                 src = Nib + (size_t)(n0) * K + k0;
#pragma unroll
        for (int rr = 0; rr < 2; rr++) {
            const int row = lj * 2 + rr;
            const int8_t* s0 = src + (size_t)row * K;
#pragma unroll
            for (int kc = 0; kc < 4; kc++)
                cp16(st + tile_off(row, kc), s0 + kc * 16);
        }
        if (tid < 128)
            cp4(ssc + (uint32_t)(c % 3) * 512 + tid * 4,
                Sc + (size_t)(n0 + tid) * KG + c);
        cp_commit();
    };

    load_stage(0);
    if (NC > 1) load_stage(1);

    const int lrow16 = lane & 15;
    const int lhi    = lane >> 4;
    const float dsc[3] = { 1.0f, 1.0f / 128.0f, 1.0f / 16384.0f };

    for (int c = 0; c < NC; c++) {
        if (c + 1 < NC) cp_wait<1>();
        else            cp_wait<0>();
        __syncthreads();

        const uint32_t st = sb + (uint32_t)(c % 3) * I8_STAGE;
        const float* ss = (const float*)(smem + 3 * I8_STAGE + (c % 3) * 512);

        // cache B (nib) fragments for both k32 halves
        uint32_t bfr[2][4][4];
#pragma unroll
        for (int kb = 0; kb < 2; kb++)
#pragma unroll
            for (int g = 0; g < 4; g++)
                ldm_x4(bfr[kb][g],
                       st + 3 * I8_TILE + tile_off(wn + g * 16 + lrow16, kb * 2 + lhi));

#pragma unroll
        for (int d = 0; d < 3; d++) {
            int acc32[2][8][4];
#pragma unroll
            for (int i = 0; i < 2; i++)
#pragma unroll
                for (int j = 0; j < 8; j++)
#pragma unroll
                    for (int v = 0; v < 4; v++) acc32[i][j][v] = 0;

#pragma unroll
            for (int kb = 0; kb < 2; kb++) {
                uint32_t af[2][4];
#pragma unroll
                for (int mt = 0; mt < 2; mt++)
                    ldm_x4(af[mt],
                           st + d * I8_TILE + tile_off(wm + mt * 16 + lrow16, kb * 2 + lhi));
#pragma unroll
                for (int g = 0; g < 4; g++)
#pragma unroll
                    for (int mt = 0; mt < 2; mt++)
#pragma unroll
                        for (int sub = 0; sub < 2; sub++)
                            mma_s8(acc32[mt][g * 2 + sub], af[mt],
                                   bfr[kb][g][sub], bfr[kb][g][sub + 2]);
            }
            // drain this digit with group scale
            const float ds = dsc[d];
#pragma unroll
            for (int g = 0; g < 4; g++)
#pragma unroll
                for (int sub = 0; sub < 2; sub++) {
                    const int nn = wn + g * 16 + sub * 8 + (lane & 3) * 2;
                    const float s0 = ss[nn] * ds;
                    const float s1 = ss[nn + 1] * ds;
#pragma unroll
                    for (int mt = 0; mt < 2; mt++) {
                        float* f = accf[mt][g * 2 + sub];
                        const int* a = acc32[mt][g * 2 + sub];
                        f[0] += (float)a[0] * s0;
                        f[1] += (float)a[1] * s1;
                        f[2] += (float)a[2] * s0;
                        f[3] += (float)a[3] * s1;
                    }
                }
        }
        if (c + 2 < NC) load_stage(c + 2);
    }

    // epilogue: multiply by per-row activation scale
#pragma unroll
    for (int mt = 0; mt < 2; mt++) {
        const int mrow = m0 + wm + mt * 16 + (lane >> 2);
        const float sa0 = Sa[mrow];
        const float sa1 = Sa[mrow + 8];
#pragma unroll
        for (int g = 0; g < 4; g++)
#pragma unroll
            for (int sub = 0; sub < 2; sub++) {
                const float* d = accf[mt][g * 2 + sub];
                const int n = n0 + wn + g * 16 + sub * 8 + (lane & 3) * 2;
                *(float2*)(C + (size_t)mrow * ldc + n) =
                    make_float2(d[0] * sa0, d[1] * sa0);
                *(float2*)(C + (size_t)(mrow + 8) * ldc + n) =
                    make_float2(d[2] * sa1, d[3] * sa1);
            }
    }
}

// ---------------------------------------------------------------------------
// GEMM3: score-path fp16 split GEMM (QK^T).  Main hi*hi in f32 acc, cross
// terms in f16 acc.  CTA 128x128, BK=32, 3-stage, 256 threads, 4x2 warps.
// causal==1: skip tile if n0 > m0+127.
// ---------------------------------------------------------------------------
#define G_TILE 8192
#define G3_STAGE (4 * G_TILE)
#define G3_SMEM  (3 * G3_STAGE)
#define G1_STAGE (2 * G_TILE)
#define G1_SMEM  (3 * G1_STAGE)

__global__ __launch_bounds__(256, 1) void gemm3(
    const h16* __restrict__ Ah, const h16* __restrict__ Al,
    const h16* __restrict__ Bh, const h16* __restrict__ Bl,
    float* __restrict__ Cb,
    int K, int lda, int ldb, int ldc,
    long a_hs, long b_hs, int b_div, long c_hs,
    float alpha, int causal)
{
    const int m0 = blockIdx.y * 128;
    const int n0 = blockIdx.x * 128;
    if (causal == 1 && n0 > m0 + 127) return;

    extern __shared__ char smem[];
    const uint32_t sb = smem_u32(smem);
    const int tid  = threadIdx.x;
    const int wid  = tid >> 5;
    const int lane = tid & 31;
    const int h = blockIdx.z;

    const h16* ah = Ah + (long)h * a_hs;
    const h16* al = Al + (long)h * a_hs;
    const h16* bh = Bh + (long)(h / b_div) * b_hs;
    const h16* bl = Bl + (long)(h / b_div) * b_hs;
    float* C = Cb + (long)h * c_hs;

    const int NC = K >> 5;
    const int wm = (wid & 3) * 32;
    const int wn = (wid >> 2) * 64;

    float    accf[2][8][4];
    uint32_t accc[2][8][2];
#pragma unroll
    for (int i = 0; i < 2; i++)
#pragma unroll
        for (int j = 0; j < 8; j++) {
#pragma unroll
            for (int v = 0; v < 4; v++) accf[i][j][v] = 0.0f;
            accc[i][j][0] = 0u; accc[i][j][1] = 0u;
        }

    const int lrow = tid & 127;
    const int pair = tid >> 7;
    auto load_stage = [&](int c) {
        const int k0 = c << 5;
        const uint32_t st = sb + (uint32_t)(c % 3) * G3_STAGE;
        const h16* s0;
        const h16* s1;
        uint32_t b0, b1;
        if (pair == 0) {
            s0 = ah + (size_t)(m0 + lrow) * lda + k0;
            s1 = al + (size_t)(m0 + lrow) * lda + k0;
            b0 = st; b1 = st + G_TILE;
        } else {
            s0 = bh + (size_t)(n0 + lrow) * ldb + k0;
            s1 = bl + (size_t)(n0 + lrow) * ldb + k0;
            b0 = st + 2 * G_TILE; b1 = st + 3 * G_TILE;
        }
#pragma unroll
        for (int kc = 0; kc < 4; kc++) {
            const uint32_t off = tile_off(lrow, kc);
            cp16(b0 + off, s0 + kc * 8);
            cp16(b1 + off, s1 + kc * 8);
        }
        cp_commit();
    };

    load_stage(0);
    if (NC > 1) load_stage(1);

    const int lrow16 = lane & 15;
    const int lhi    = lane >> 4;

    for (int c = 0; c < NC; c++) {
        if (c + 1 < NC) cp_wait<1>();
        else            cp_wait<0>();
        __syncthreads();

        const uint32_t st = sb + (uint32_t)(c % 3) * G3_STAGE;

#pragma unroll
        for (int kb2 = 0; kb2 < 2; kb2++) {
            const int kcb = kb2 * 2;
            uint32_t afh[2][4], afl[2][4];
#pragma unroll
            for (int mt = 0; mt < 2; mt++) {
                const uint32_t off = tile_off(wm + mt * 16 + lrow16, kcb + lhi);
                ldm_x4(afh[mt], st + 0 * G_TILE + off);
                ldm_x4(afl[mt], st + 1 * G_TILE + off);
            }
#pragma unroll
            for (int g = 0; g < 4; g++) {
                const uint32_t boff = tile_off(wn + g * 16 + lrow16, kcb + lhi);
                uint32_t bhf[4], blf[4];
                ldm_x4(bhf, st + 2 * G_TILE + boff);
                ldm_x4(blf, st + 3 * G_TILE + boff);
#pragma unroll
                for (int mt = 0; mt < 2; mt++) {
#pragma unroll
                    for (int sub = 0; sub < 2; sub++) {
                        mma_f32(accf[mt][g * 2 + sub], afh[mt], bhf[sub], bhf[sub + 2]);
                        mma_f16(accc[mt][g * 2 + sub], afh[mt], blf[sub], blf[sub + 2]);
                        mma_f16(accc[mt][g * 2 + sub], afl[mt], bhf[sub], bhf[sub + 2]);
                    }
                }
            }
        }
        if (c + 2 < NC) load_stage(c + 2);
    }

#pragma unroll
    for (int mt = 0; mt < 2; mt++) {
        const int mrow = m0 + wm + mt * 16 + (lane >> 2);
#pragma unroll
        for (int g = 0; g < 4; g++) {
#pragma unroll
            for (int sub = 0; sub < 2; sub++) {
                const float* d = accf[mt][g * 2 + sub];
                const __half2 c0 = *(const __half2*)&accc[mt][g * 2 + sub][0];
                const __half2 c1 = *(const __half2*)&accc[mt][g * 2 + sub][1];
                const int n = n0 + wn + g * 16 + sub * 8 + (lane & 3) * 2;
                *(float2*)(C + (size_t)mrow * ldc + n) =
                    make_float2((d[0] + __low2float(c0)) * alpha,
                                (d[1] + __high2float(c0)) * alpha);
                *(float2*)(C + (size_t)(mrow + 8) * ldc + n) =
                    make_float2((d[2] + __low2float(c1)) * alpha,
                                (d[3] + __high2float(c1)) * alpha);
            }
        }
    }
}

// ---------------------------------------------------------------------------
// GEMM1: value-path plain fp16 GEMM, fp32 acc.  causal==2: K <= m0+128 (PV).
// ---------------------------------------------------------------------------
__global__ __launch_bounds__(256, 2) void gemm1(
    const h16* __restrict__ Ab, const h16* __restrict__ Bb,
    float* __restrict__ Cb,
    int K, int lda, int ldb, int ldc,
    long a_hs, long b_hs, int b_div, long c_hs,
    float alpha, int causal)
{
    const int m0 = blockIdx.y * 128;
    const int n0 = blockIdx.x * 128;

    extern __shared__ char smem[];
    const uint32_t sb = smem_u32(smem);
    const int tid  = threadIdx.x;
    const int wid  = tid >> 5;
    const int lane = tid & 31;
    const int h = blockIdx.z;

    const h16* A = Ab + (long)h * a_hs;
    const h16* B = Bb + (long)(h / b_div) * b_hs;
    float* C = Cb + (long)h * c_hs;

    const int kmax = (causal == 2) ? min(K, m0 + 128) : K;
    const int NC = kmax >> 5;

    const int wm = (wid & 3) * 32;
    const int wn = (wid >> 2) * 64;

    float accf[2][8][4];
#pragma unroll
    for (int i = 0; i < 2; i++)
#pragma unroll
        for (int j = 0; j < 8; j++)
#pragma unroll
            for (int v = 0; v < 4; v++) accf[i][j][v] = 0.0f;

    const int lrow = tid & 127;
    const int arr  = tid >> 7;
    auto load_stage = [&](int c) {
        const int k0 = c << 5;
        const uint32_t st = sb + (uint32_t)(c % 3) * G1_STAGE;
        const h16* s0 = arr ? (B + (size_t)(n0 + lrow) * ldb + k0)
                            : (A + (size_t)(m0 + lrow) * lda + k0);
        const uint32_t b0 = st + (uint32_t)arr * G_TILE;
#pragma unroll
        for (int kc = 0; kc < 4; kc++)
            cp16(b0 + tile_off(lrow, kc), s0 + kc * 8);
        cp_commit();
    };

    load_stage(0);
    if (NC > 1) load_stage(1);

    const int lrow16 = lane & 15;
    const int lhi    = lane >> 4;

    for (int c = 0; c < NC; c++) {
        if (c + 1 < NC) cp_wait<1>();
        else            cp_wait<0>();
        __syncthreads();

        const uint32_t st = sb + (uint32_t)(c % 3) * G1_STAGE;

#pragma unroll
        for (int kb2 = 0; kb2 < 2; kb2++) {
            const int kcb = kb2 * 2;
            uint32_t af[2][4];
#pragma unroll
            for (int mt = 0; mt < 2; mt++)
                ldm_x4(af[mt], st + tile_off(wm + mt * 16 + lrow16, kcb + lhi));
#pragma unroll
            for (int g = 0; g < 4; g++) {
                uint32_t bf[4];
                ldm_x4(bf, st + G_TILE + tile_off(wn + g * 16 + lrow16, kcb + lhi));
#pragma unroll
                for (int mt = 0; mt < 2; mt++) {
#pragma unroll
                    for (int sub = 0; sub < 2; sub++)
                        mma_f32(accf[mt][g * 2 + sub], af[mt], bf[sub], bf[sub + 2]);
                }
            }
        }
        if (c + 2 < NC) load_stage(c + 2);
    }

#pragma unroll
    for (int mt = 0; mt < 2; mt++) {
        const int mrow = m0 + wm + mt * 16 + (lane >> 2);
#pragma unroll
        for (int g = 0; g < 4; g++) {
#pragma unroll
            for (int sub = 0; sub < 2; sub++) {
                const float* d = accf[mt][g * 2 + sub];
                const int n = n0 + wn + g * 16 + sub * 8 + (lane & 3) * 2;
                *(float2*)(C + (size_t)mrow * ldc + n) =
                    make_float2(d[0] * alpha, d[1] * alpha);
                *(float2*)(C + (size_t)(mrow + 8) * ldc + n) =
                    make_float2(d[2] * alpha, d[3] * alpha);
            }
        }
    }
}

// ---------------------------------------------------------------------------
// Launch
// ---------------------------------------------------------------------------
extern "C" void kernel_launch(void* const* d_in, const int* in_sizes, int n_in,
                              void* d_out, int out_size)
{
    (void)in_sizes; (void)n_in; (void)out_size;
    const float* x    = (const float*)d_in[0];
    const void*  wq   = d_in[1];
    const float* sq   = (const float*)d_in[2];
    const void*  wk   = d_in[3];
    const float* sk   = (const float*)d_in[4];
    const void*  wv   = d_in[5];
    const float* sv   = (const float*)d_in[6];
    const void*  wo   = d_in[7];
    const float* so   = (const float*)d_in[8];
    const float* cosb = (const float*)d_in[9];
    const float* sinb = (const float*)d_in[10];
    float* out = (float*)d_out;

    float *xq, *xk, *xv, *sc, *att, *sa;
    h16 *xh, *qh, *ql, *kh, *kl, *vth, *ath, *ph, *wvh, *woh;
    int8_t *xd0, *xd1, *xd2, *nibq, *nibk;
    int8_t *wq8, *wk8, *wv8, *wo8;

    cudaGetSymbolAddress((void**)&xq,  g_xq);
    cudaGetSymbolAddress((void**)&xk,  g_xk);
    cudaGetSymbolAddress((void**)&xv,  g_xv);
    cudaGetSymbolAddress((void**)&sc,  g_sc);
    cudaGetSymbolAddress((void**)&att, g_att);
    cudaGetSymbolAddress((void**)&sa,  g_sa);
    cudaGetSymbolAddress((void**)&xh,  g_xh);
    cudaGetSymbolAddress((void**)&qh,  g_qh);   cudaGetSymbolAddress((void**)&ql,  g_ql);
    cudaGetSymbolAddress((void**)&kh,  g_kh);   cudaGetSymbolAddress((void**)&kl,  g_kl);
    cudaGetSymbolAddress((void**)&vth, g_vth);
    cudaGetSymbolAddress((void**)&ath, g_ath);
    cudaGetSymbolAddress((void**)&ph,  g_ph);
    cudaGetSymbolAddress((void**)&wvh, g_wvh);
    cudaGetSymbolAddress((void**)&woh, g_woh);
    cudaGetSymbolAddress((void**)&xd0, g_xd0);  cudaGetSymbolAddress((void**)&xd1, g_xd1);
    cudaGetSymbolAddress((void**)&xd2, g_xd2);
    cudaGetSymbolAddress((void**)&nibq, g_nibq); cudaGetSymbolAddress((void**)&nibk, g_nibk);
    cudaGetSymbolAddress((void**)&wq8, g_wq8);  cudaGetSymbolAddress((void**)&wk8, g_wk8);
    cudaGetSymbolAddress((void**)&wv8, g_wv8);  cudaGetSymbolAddress((void**)&wo8, g_wo8);

    cudaFuncSetAttribute(gemm_i8, cudaFuncAttributeMaxDynamicSharedMemorySize, I8_SMEM);
    cudaFuncSetAttribute(gemm3,  cudaFuncAttributeMaxDynamicSharedMemorySize, G3_SMEM);
    cudaFuncSetAttribute(gemm1,  cudaFuncAttributeMaxDynamicSharedMemorySize, G1_SMEM);

    const dim3 blk(256);
    const long nq = (long)DM * DM / 2;
    const long nk = (long)KVD * DM / 2;

    // ingest q-path first; launch #6 = gemm_i8 q-proj (ncu window)
    probe_mode<<<1, 32>>>((const int*)wq);                                 // 1
    repack_w<<<1024, blk>>>(wq, wq8, nq);                                  // 2
    unpack_nib<<<2048, blk>>>(wq8, nibq, (long)DM * DM);                   // 3
    quant_x3<<<SEQ, blk>>>(x, xd0, xd1, xd2, sa);                          // 4
    cvt_f32h<<<2048, blk>>>(x, xh, (long)SEQ * DM);                        // 5
    gemm_i8<<<dim3(DM / 128, SEQ / 128), blk, I8_SMEM>>>(                  // 6 (ncu)
        xd0, xd1, xd2, nibq, sq, sa, xq, DM, DM);

    repack_w<<<1024, blk>>>(wk, wk8, nk);
    repack_w<<<1024, blk>>>(wv, wv8, nk);
    repack_w<<<1024, blk>>>(wo, wo8, nq);
    unpack_nib<<<2048, blk>>>(wk8, nibk, (long)KVD * DM);
    dequant_plain_w<<<2048, blk>>>(wv8, sv, wvh, (long)KVD * DM);
    dequant_plain_w<<<2048, blk>>>(wo8, so, woh, (long)DM * DM);

    // k-proj (IMMA), v-proj (fp16 1-term)
    gemm_i8<<<dim3(KVD / 128, SEQ / 128), blk, I8_SMEM>>>(
        xd0, xd1, xd2, nibk, sk, sa, xk, DM, KVD);
    gemm1<<<dim3(KVD / 128, SEQ / 128, 1), blk, G1_SMEM>>>(
        xh, wvh, xv, DM, DM, DM, KVD, 0, 0, 1, 0, 1.0f, 0);

    // RoPE (+1/sqrt(HD) on q) -> fp16 splits; V transpose
    rope_split<<<(SEQ * NH  * 64 + 255) / 256, blk>>>(xq, cosb, sinb, qh, ql, NH,
                                                      0.08838834764831843f);
    rope_split<<<(SEQ * NKV * 64 + 255) / 256, blk>>>(xk, cosb, sinb, kh, kl, NKV, 1.0f);
    vtrans_h<<<(NKV * HD * SEQ + 255) / 256, blk>>>(xv, vth);

    // scores = (q/sqrt(HD)) K^T  (fp16 3-term, lower-triangular tiles)
    gemm3<<<dim3(SEQ / 128, SEQ / 128, NH), blk, G3_SMEM>>>(
        qh, ql, kh, kl, sc, HD, DM, KVD, SEQ,
        (long)HD, (long)HD, NH / NKV, (long)SEQ * SEQ, 1.0f, 1);

    // causal softmax -> fp16 probs
    softmax_h<<<NH * SEQ, 128>>>(sc, ph);

    // att = P V  (fp16 1-term, k-limited)
    gemm1<<<dim3(HD / 128, SEQ / 128, NH), blk, G1_SMEM>>>(
        ph, vth, att, SEQ, SEQ, SEQ, DM,
        (long)SEQ * SEQ, (long)HD * SEQ, NH / NKV, (long)HD, 1.0f, 2);

    // output projection (fp16 1-term)
    cvt_f32h<<<2048, blk>>>(att, ath, (long)SEQ * DM);
    gemm1<<<dim3(DM / 128, SEQ / 128, 1), blk, G1_SMEM>>>(
        ath, woh, out, DM, DM, DM, DM, 0, 0, 1, 0, 1.0f, 0);
}

// round 8
// speedup vs baseline: 1.4823x; 1.4823x over previous
#include <cuda_runtime.h>
#include <cuda_fp16.h>
#include <cstdint>

// ---------------------------------------------------------------------------
// Problem constants
// ---------------------------------------------------------------------------
#define SEQ   2048
#define DM    4096
#define NH    32
#define NKV   8
#define HD    128
#define KVD   (NKV * HD)   // 1024

typedef __half h16;

// ---------------------------------------------------------------------------
// Device-global scratch (allocation-free rule)
// ---------------------------------------------------------------------------
__device__ float g_xq[SEQ * DM];
__device__ float g_xk[SEQ * KVD];
__device__ float g_xv[SEQ * KVD];
__device__ float g_sc[(size_t)NH * SEQ * SEQ];     // fp32 scores
__device__ float g_att[SEQ * DM];

// fp16 operands
__device__ __align__(16) h16 g_xh [SEQ * DM],  g_xl [SEQ * DM];  // x split
__device__ __align__(16) h16 g_qh [SEQ * DM],  g_ql [SEQ * DM];  // q split (QK)
__device__ __align__(16) h16 g_kh [SEQ * KVD], g_kl [SEQ * KVD]; // k split (QK)
__device__ __align__(16) h16 g_vth[NKV * HD * SEQ];              // V^T plain
__device__ __align__(16) h16 g_ath[SEQ * DM];                    // att plain
__device__ __align__(16) h16 g_ph [(size_t)NH * SEQ * SEQ];      // probs plain

// exact fp16 nibble planes (weight = nib * group_scale)
__device__ __align__(16) h16 g_nibq[DM * DM];
__device__ __align__(16) h16 g_nibk[KVD * DM];
__device__ __align__(16) h16 g_nibv[KVD * DM];
__device__ __align__(16) h16 g_nibo[DM * DM];

// canonical int8 packed weights
__device__ int8_t g_wq8[DM * DM / 2];
__device__ int8_t g_wk8[KVD * DM / 2];
__device__ int8_t g_wv8[KVD * DM / 2];
__device__ int8_t g_wo8[DM * DM / 2];
__device__ int    g_mode;

// ---------------------------------------------------------------------------
// PTX helpers (base sm_103 ISA: cp.async / ldmatrix / mma.sync)
// ---------------------------------------------------------------------------
__device__ __forceinline__ uint32_t smem_u32(const void* p) {
    uint32_t a;
    asm("{ .reg .u64 t; cvta.to.shared.u64 t, %1; cvt.u32.u64 %0, t; }" : "=r"(a) : "l"(p));
    return a;
}
__device__ __forceinline__ void cp16(uint32_t dst, const void* src) {
    asm volatile("cp.async.cg.shared.global [%0], [%1], 16;" :: "r"(dst), "l"(src) : "memory");
}
__device__ __forceinline__ void cp4(uint32_t dst, const void* src) {
    asm volatile("cp.async.ca.shared.global [%0], [%1], 4;" :: "r"(dst), "l"(src) : "memory");
}
__device__ __forceinline__ void cp_commit() {
    asm volatile("cp.async.commit_group;" ::: "memory");
}
template <int N>
__device__ __forceinline__ void cp_wait() {
    asm volatile("cp.async.wait_group %0;" :: "n"(N) : "memory");
}
__device__ __forceinline__ void ldm_x4(uint32_t* r, uint32_t addr) {
    asm volatile("ldmatrix.sync.aligned.m8n8.x4.shared.b16 {%0,%1,%2,%3}, [%4];"
                 : "=r"(r[0]), "=r"(r[1]), "=r"(r[2]), "=r"(r[3]) : "r"(addr));
}
// fp16 MMA, fp32 accumulate
__device__ __forceinline__ void mma_f32(float* d, const uint32_t* a,
                                        uint32_t b0, uint32_t b1) {
    asm volatile(
        "mma.sync.aligned.m16n8k16.row.col.f32.f16.f16.f32 "
        "{%0,%1,%2,%3}, {%4,%5,%6,%7}, {%8,%9}, {%0,%1,%2,%3};"
        : "+f"(d[0]), "+f"(d[1]), "+f"(d[2]), "+f"(d[3])
        : "r"(a[0]), "r"(a[1]), "r"(a[2]), "r"(a[3]), "r"(b0), "r"(b1));
}
// fp16 MMA, fp16 accumulate (small cross terms in QK)
__device__ __forceinline__ void mma_f16(uint32_t* d, const uint32_t* a,
                                        uint32_t b0, uint32_t b1) {
    asm volatile(
        "mma.sync.aligned.m16n8k16.row.col.f16.f16.f16.f16 "
        "{%0,%1}, {%2,%3,%4,%5}, {%6,%7}, {%0,%1};"
        : "+r"(d[0]), "+r"(d[1])
        : "r"(a[0]), "r"(a[1]), "r"(a[2]), "r"(a[3]), "r"(b0), "r"(b1));
}

// Permuted conflict-free smem layouts: atom = 8 rows x 16B, 128B blocks.
// 32-k16-wide fp16 tile (4 chunks/row):
__device__ __forceinline__ uint32_t tile_off(int row, int kc) {
    return (uint32_t)((((row >> 3) * 4 + kc) << 7) + ((row & 7) << 4));
}
// 64-k16-wide fp16 tile (8 chunks/row):
__device__ __forceinline__ uint32_t off8(int row, int kc) {
    return (uint32_t)((((row >> 3) * 8 + kc) << 7) + ((row & 7) << 4));
}

// ---------------------------------------------------------------------------
// Probe + repack (dtype-robust weight ingestion)
// ---------------------------------------------------------------------------
__global__ void probe_mode(const int* __restrict__ w)
{
    if (threadIdx.x == 0 && blockIdx.x == 0) {
        int ok = 0;
        for (int i = 0; i < 256; i++) {
            const int v = w[i];
            if (v >= -128 && v <= 127) ok++;
        }
        g_mode = (ok >= 250) ? 1 : 0;
    }
}
__global__ __launch_bounds__(256) void repack_w(
    const void* __restrict__ in, int8_t* __restrict__ out, long n)
{
    const int mode = g_mode;
    const long stride = (long)gridDim.x * blockDim.x;
    for (long i = (long)blockIdx.x * blockDim.x + threadIdx.x; i < n; i += stride) {
        if (mode) out[i] = (int8_t)((const int*)in)[i];
        else      out[i] = ((const int8_t*)in)[i];
    }
}

// Unpack Q4_0 nibbles to planar fp16 (exact, no scale).
__global__ __launch_bounds__(256) void unpack_nib_h(
    const int8_t* __restrict__ w8, h16* __restrict__ nib, long n)
{
    const long stride = (long)gridDim.x * blockDim.x;
    for (long f = (long)blockIdx.x * blockDim.x + threadIdx.x; f < n; f += stride) {
        const long r = f >> 7;
        const int  q = (int)(f & 127);
        const int8_t b = w8[r * 64 + (q & 63)];
        const int v = (q < 64) ? (b >> 4) : (((int8_t)(b << 4)) >> 4);
        nib[f] = __float2half((float)v);
    }
}

// fp32 -> fp16 hi/lo split, and plain convert
__global__ __launch_bounds__(256) void split_f32(
    const float* __restrict__ src, h16* __restrict__ hi, h16* __restrict__ lo, long n)
{
    const long stride = (long)gridDim.x * blockDim.x;
    for (long i = (long)blockIdx.x * blockDim.x + threadIdx.x; i < n; i += stride) {
        const float v = src[i];
        const h16 h = __float2half(v);
        hi[i] = h;
        lo[i] = __float2half(v - __half2float(h));
    }
}
__global__ __launch_bounds__(256) void cvt_f32h(
    const float* __restrict__ src, h16* __restrict__ dst, long n)
{
    const long stride = (long)gridDim.x * blockDim.x;
    for (long i = (long)blockIdx.x * blockDim.x + threadIdx.x; i < n; i += stride)
        dst[i] = __float2half(src[i]);
}

// ---------------------------------------------------------------------------
// RoPE (rotate-half) + optional scale + fp16 split.  x laid out [S, nh, HD].
// ---------------------------------------------------------------------------
__global__ __launch_bounds__(256) void rope_split(
    const float* __restrict__ x, const float* __restrict__ cosb,
    const float* __restrict__ sinb, h16* __restrict__ oh, h16* __restrict__ ol,
    int nheads, float scale)
{
    const long total = (long)SEQ * nheads * 64;
    long idx = (long)blockIdx.x * blockDim.x + threadIdx.x;
    if (idx >= total) return;
    const int d = (int)(idx & 63);
    const int h = (int)((idx >> 6) % nheads);
    const int s = (int)(idx / ((long)64 * nheads));
    const size_t base = (size_t)s * nheads * HD + h * HD + d;
    const float c  = cosb[s * 64 + d];
    const float sn = sinb[s * 64 + d];
    const float lo = x[base];
    const float hi = x[base + 64];
    const float r0 = (lo * c - hi * sn) * scale;
    const float r1 = (hi * c + lo * sn) * scale;
    h16 h0 = __float2half(r0);
    h16 h1 = __float2half(r1);
    oh[base]      = h0;
    ol[base]      = __float2half(r0 - __half2float(h0));
    oh[base + 64] = h1;
    ol[base + 64] = __float2half(r1 - __half2float(h1));
}

// ---------------------------------------------------------------------------
// Transpose V to plain fp16: vt[kv][d][s] = xv[s][kv*HD + d]
// ---------------------------------------------------------------------------
__global__ __launch_bounds__(256) void vtrans_h(
    const float* __restrict__ xv, h16* __restrict__ vt)
{
    const long total = (long)NKV * HD * SEQ;
    long idx = (long)blockIdx.x * blockDim.x + threadIdx.x;
    if (idx >= total) return;
    const int s  = (int)(idx % SEQ);
    const int d  = (int)((idx / SEQ) % HD);
    const int kv = (int)(idx / ((long)SEQ * HD));
    vt[idx] = __float2half(xv[(size_t)s * KVD + kv * HD + d]);
}

// ---------------------------------------------------------------------------
// Causal row softmax: fp32 scores -> plain fp16 probs, zero-filled to the
// next 128 boundary.
// ---------------------------------------------------------------------------
__global__ __launch_bounds__(128) void softmax_h(
    const float* __restrict__ sc, h16* __restrict__ ph)
{
    const int row = blockIdx.x;          // h*SEQ + q
    const int q   = row & (SEQ - 1);
    const float* p = sc + (size_t)row * SEQ;
    h16* oh = ph + (size_t)row * SEQ;
    const int len  = q + 1;
    const int zend = ((q >> 7) + 1) << 7;
    const int tid  = threadIdx.x;

    __shared__ float red[4];

    float m = -1e30f;
    for (int k = tid; k < len; k += 128) m = fmaxf(m, p[k]);
#pragma unroll
    for (int o = 16; o > 0; o >>= 1) m = fmaxf(m, __shfl_xor_sync(0xffffffffu, m, o));
    if ((tid & 31) == 0) red[tid >> 5] = m;
    __syncthreads();
    m = fmaxf(fmaxf(red[0], red[1]), fmaxf(red[2], red[3]));
    __syncthreads();

    float sum = 0.0f;
    for (int k = tid; k < len; k += 128) sum += __expf(p[k] - m);
#pragma unroll
    for (int o = 16; o > 0; o >>= 1) sum += __shfl_xor_sync(0xffffffffu, sum, o);
    if ((tid & 31) == 0) red[tid >> 5] = sum;
    __syncthreads();
    sum = red[0] + red[1] + red[2] + red[3];

    const float inv = 1.0f / sum;
    for (int k = tid; k < len; k += 128)
        oh[k] = __float2half(__expf(p[k] - m) * inv);
    const h16 z = __float2half(0.0f);
    for (int k = len + tid; k < zend; k += 128) oh[k] = z;
}

// ---------------------------------------------------------------------------
// GEMM_W4: projection GEMM with exact fp16 nibble weights + fp32 group scales.
//   C[m][n] = sum_g s[n][g] * sum_{k in g} (Ah [+Al])[m,k] * nib[n,k]
// CTA 128x128, BK=64 (= one scale group), 3-stage cp.async, 256 threads,
// 8 warps 4x2 (warp tile 32x64). Per-chunk fp32 group acc, drained with s.
// TWO=1: two activation terms (projection exact); TWO=0: one term.
// ---------------------------------------------------------------------------
#define W4_TILE   16384                      // 128 x 64 fp16
#define W4_STAGE  (3 * W4_TILE)              // Ah, Al, nib : 48 KB
#define W4_SMEM   (3 * W4_STAGE + 3 * 512)   // + per-stage scale row

template <int TWO>
__global__ __launch_bounds__(256, 1) void gemm_w4(
    const h16* __restrict__ Ah, const h16* __restrict__ Al,
    const h16* __restrict__ Nib, const float* __restrict__ Sc,
    float* __restrict__ C, int K, int ldc)
{
    const int m0 = blockIdx.y * 128;
    const int n0 = blockIdx.x * 128;

    extern __shared__ char smem[];
    const uint32_t sb  = smem_u32(smem);
    const uint32_t ssc = sb + 3 * W4_STAGE;
    const int tid  = threadIdx.x;
    const int wid  = tid >> 5;
    const int lane = tid & 31;

    const int NC = K >> 6;
    const int KG = K >> 6;

    const int wm = (wid & 3) * 32;
    const int wn = (wid >> 2) * 64;

    float accf[2][8][4];
#pragma unroll
    for (int i = 0; i < 2; i++)
#pragma unroll
        for (int j = 0; j < 8; j++)
#pragma unroll
            for (int v = 0; v < 4; v++) accf[i][j][v] = 0.0f;

    const int ntiles = TWO ? 3 : 2;
    auto load_stage = [&](int c) {
        const int k0 = c << 6;
        const uint32_t st = sb + (uint32_t)(c % 3) * W4_STAGE;
        const int total = ntiles << 10;           // tiles * 128 rows * 8 chunks
        for (int i = tid; i < total; i += 256) {
            const int tile = i >> 10;
            const int row  = (i >> 3) & 127;
            const int kc   = i & 7;
            const h16* src;
            uint32_t dstb;
            if (tile == 0)            { src = Ah  + (size_t)(m0 + row) * K + k0; dstb = st; }
            else if (TWO && tile == 1){ src = Al  + (size_t)(m0 + row) * K + k0; dstb = st + W4_TILE; }
            else                      { src = Nib + (size_t)(n0 + row) * K + k0; dstb = st + 2 * W4_TILE; }
            cp16(dstb + off8(row, kc), src + kc * 8);
        }
        if (tid < 128)
            cp4(ssc + (uint32_t)(c % 3) * 512 + tid * 4,
                Sc + (size_t)(n0 + tid) * KG + c);
        cp_commit();
    };

    load_stage(0);
    if (NC > 1) load_stage(1);

    const int lrow16 = lane & 15;
    const int lhi    = lane >> 4;

    for (int c = 0; c < NC; c++) {
        if (c + 1 < NC) cp_wait<1>();
        else            cp_wait<0>();
        __syncthreads();

        const uint32_t st = sb + (uint32_t)(c % 3) * W4_STAGE;
        const float* ss = (const float*)(smem + 3 * W4_STAGE + (c % 3) * 512);

        float accg[2][8][4];
#pragma unroll
        for (int i = 0; i < 2; i++)
#pragma unroll
            for (int j = 0; j < 8; j++)
#pragma unroll
                for (int v = 0; v < 4; v++) accg[i][j][v] = 0.0f;

#pragma unroll
        for (int kb = 0; kb < 4; kb++) {
            uint32_t afh[2][4], afl[2][4];
#pragma unroll
            for (int mt = 0; mt < 2; mt++) {
                const uint32_t off = off8(wm + mt * 16 + lrow16, kb * 2 + lhi);
                ldm_x4(afh[mt], st + off);
                if (TWO) ldm_x4(afl[mt], st + W4_TILE + off);
            }
#pragma unroll
            for (int g = 0; g < 4; g++) {
                uint32_t bf[4];
                ldm_x4(bf, st + 2 * W4_TILE + off8(wn + g * 16 + lrow16, kb * 2 + lhi));
#pragma unroll
                for (int mt = 0; mt < 2; mt++) {
#pragma unroll
                    for (int sub = 0; sub < 2; sub++) {
                        mma_f32(accg[mt][g * 2 + sub], afh[mt], bf[sub], bf[sub + 2]);
                        if (TWO)
                            mma_f32(accg[mt][g * 2 + sub], afl[mt], bf[sub], bf[sub + 2]);
                    }
                }
            }
        }

        // drain group acc with per-n scale for this group
#pragma unroll
        for (int g = 0; g < 4; g++)
#pragma unroll
            for (int sub = 0; sub < 2; sub++) {
                const int nn = wn + g * 16 + sub * 8 + (lane & 3) * 2;
                const float s0 = ss[nn];
                const float s1 = ss[nn + 1];
#pragma unroll
                for (int mt = 0; mt < 2; mt++) {
                    float* f = accf[mt][g * 2 + sub];
                    const float* a = accg[mt][g * 2 + sub];
                    f[0] += a[0] * s0;
                    f[1] += a[1] * s1;
                    f[2] += a[2] * s0;
                    f[3] += a[3] * s1;
                }
            }

        if (c + 2 < NC) load_stage(c + 2);
    }

#pragma unroll
    for (int mt = 0; mt < 2; mt++) {
        const int mrow = m0 + wm + mt * 16 + (lane >> 2);
#pragma unroll
        for (int g = 0; g < 4; g++)
#pragma unroll
            for (int sub = 0; sub < 2; sub++) {
                const float* d = accf[mt][g * 2 + sub];
                const int n = n0 + wn + g * 16 + sub * 8 + (lane & 3) * 2;
                *(float2*)(C + (size_t)mrow * ldc + n)       = make_float2(d[0], d[1]);
                *(float2*)(C + (size_t)(mrow + 8) * ldc + n) = make_float2(d[2], d[3]);
            }
    }
}

// ---------------------------------------------------------------------------
// GEMM3: QK^T fp16 split GEMM (3 terms; cross terms in f16 acc).
// CTA 128x128, BK=32, 3-stage, 256 threads, 4x2 warps.
// causal==1: skip tile if n0 > m0+127.
// ---------------------------------------------------------------------------
#define G_TILE 8192
#define G3_STAGE (4 * G_TILE)
#define G3_SMEM  (3 * G3_STAGE)
#define G1_STAGE (2 * G_TILE)
#define G1_SMEM  (3 * G1_STAGE)

__global__ __launch_bounds__(256, 1) void gemm3(
    const h16* __restrict__ Ah, const h16* __restrict__ Al,
    const h16* __restrict__ Bh, const h16* __restrict__ Bl,
    float* __restrict__ Cb,
    int K, int lda, int ldb, int ldc,
    long a_hs, long b_hs, int b_div, long c_hs,
    float alpha, int causal)
{
    const int m0 = blockIdx.y * 128;
    const int n0 = blockIdx.x * 128;
    if (causal == 1 && n0 > m0 + 127) return;

    extern __shared__ char smem[];
    const uint32_t sb = smem_u32(smem);
    const int tid  = threadIdx.x;
    const int wid  = tid >> 5;
    const int lane = tid & 31;
    const int h = blockIdx.z;

    const h16* ah = Ah + (long)h * a_hs;
    const h16* al = Al + (long)h * a_hs;
    const h16* bh = Bh + (long)(h / b_div) * b_hs;
    const h16* bl = Bl + (long)(h / b_div) * b_hs;
    float* C = Cb + (long)h * c_hs;

    const int NC = K >> 5;
    const int wm = (wid & 3) * 32;
    const int wn = (wid >> 2) * 64;

    float    accf[2][8][4];
    uint32_t accc[2][8][2];
#pragma unroll
    for (int i = 0; i < 2; i++)
#pragma unroll
        for (int j = 0; j < 8; j++) {
#pragma unroll
            for (int v = 0; v < 4; v++) accf[i][j][v] = 0.0f;
            accc[i][j][0] = 0u; accc[i][j][1] = 0u;
        }

    const int lrow = tid & 127;
    const int pair = tid >> 7;
    auto load_stage = [&](int c) {
        const int k0 = c << 5;
        const uint32_t st = sb + (uint32_t)(c % 3) * G3_STAGE;
        const h16* s0;
        const h16* s1;
        uint32_t b0, b1;
        if (pair == 0) {
            s0 = ah + (size_t)(m0 + lrow) * lda + k0;
            s1 = al + (size_t)(m0 + lrow) * lda + k0;
            b0 = st; b1 = st + G_TILE;
        } else {
            s0 = bh + (size_t)(n0 + lrow) * ldb + k0;
            s1 = bl + (size_t)(n0 + lrow) * ldb + k0;
            b0 = st + 2 * G_TILE; b1 = st + 3 * G_TILE;
        }
#pragma unroll
        for (int kc = 0; kc < 4; kc++) {
            const uint32_t off = tile_off(lrow, kc);
            cp16(b0 + off, s0 + kc * 8);
            cp16(b1 + off, s1 + kc * 8);
        }
        cp_commit();
    };

    load_stage(0);
    if (NC > 1) load_stage(1);

    const int lrow16 = lane & 15;
    const int lhi    = lane >> 4;

    for (int c = 0; c < NC; c++) {
        if (c + 1 < NC) cp_wait<1>();
        else            cp_wait<0>();
        __syncthreads();

        const uint32_t st = sb + (uint32_t)(c % 3) * G3_STAGE;

#pragma unroll
        for (int kb2 = 0; kb2 < 2; kb2++) {
            const int kcb = kb2 * 2;
            uint32_t afh[2][4], afl[2][4];
#pragma unroll
            for (int mt = 0; mt < 2; mt++) {
                const uint32_t off = tile_off(wm + mt * 16 + lrow16, kcb + lhi);
                ldm_x4(afh[mt], st + 0 * G_TILE + off);
                ldm_x4(afl[mt], st + 1 * G_TILE + off);
            }
#pragma unroll
            for (int g = 0; g < 4; g++) {
                const uint32_t boff = tile_off(wn + g * 16 + lrow16, kcb + lhi);
                uint32_t bhf[4], blf[4];
                ldm_x4(bhf, st + 2 * G_TILE + boff);
                ldm_x4(blf, st + 3 * G_TILE + boff);
#pragma unroll
                for (int mt = 0; mt < 2; mt++) {
#pragma unroll
                    for (int sub = 0; sub < 2; sub++) {
                        mma_f32(accf[mt][g * 2 + sub], afh[mt], bhf[sub], bhf[sub + 2]);
                        mma_f16(accc[mt][g * 2 + sub], afh[mt], blf[sub], blf[sub + 2]);
                        mma_f16(accc[mt][g * 2 + sub], afl[mt], bhf[sub], bhf[sub + 2]);
                    }
                }
            }
        }
        if (c + 2 < NC) load_stage(c + 2);
    }

#pragma unroll
    for (int mt = 0; mt < 2; mt++) {
        const int mrow = m0 + wm + mt * 16 + (lane >> 2);
#pragma unroll
        for (int g = 0; g < 4; g++) {
#pragma unroll
            for (int sub = 0; sub < 2; sub++) {
                const float* d = accf[mt][g * 2 + sub];
                const __half2 c0 = *(const __half2*)&accc[mt][g * 2 + sub][0];
                const __half2 c1 = *(const __half2*)&accc[mt][g * 2 + sub][1];
                const int n = n0 + wn + g * 16 + sub * 8 + (lane & 3) * 2;
                *(float2*)(C + (size_t)mrow * ldc + n) =
                    make_float2((d[0] + __low2float(c0)) * alpha,
                                (d[1] + __high2float(c0)) * alpha);
                *(float2*)(C + (size_t)(mrow + 8) * ldc + n) =
                    make_float2((d[2] + __low2float(c1)) * alpha,
                                (d[3] + __high2float(c1)) * alpha);
            }
        }
    }
}

// ---------------------------------------------------------------------------
// GEMM1: PV plain fp16 GEMM, fp32 acc.  causal==2: K <= m0+128.
// ---------------------------------------------------------------------------
__global__ __launch_bounds__(256, 2) void gemm1(
    const h16* __restrict__ Ab, const h16* __restrict__ Bb,
    float* __restrict__ Cb,
    int K, int lda, int ldb, int ldc,
    long a_hs, long b_hs, int b_div, long c_hs,
    float alpha, int causal)
{
    const int m0 = blockIdx.y * 128;
    const int n0 = blockIdx.x * 128;

    extern __shared__ char smem[];
    const uint32_t sb = smem_u32(smem);
    const int tid  = threadIdx.x;
    const int wid  = tid >> 5;
    const int lane = tid & 31;
    const int h = blockIdx.z;

    const h16* A = Ab + (long)h * a_hs;
    const h16* B = Bb + (long)(h / b_div) * b_hs;
    float* C = Cb + (long)h * c_hs;

    const int kmax = (causal == 2) ? min(K, m0 + 128) : K;
    const int NC = kmax >> 5;

    const int wm = (wid & 3) * 32;
    const int wn = (wid >> 2) * 64;

    float accf[2][8][4];
#pragma unroll
    for (int i = 0; i < 2; i++)
#pragma unroll
        for (int j = 0; j < 8; j++)
#pragma unroll
            for (int v = 0; v < 4; v++) accf[i][j][v] = 0.0f;

    const int lrow = tid & 127;
    const int arr  = tid >> 7;
    auto load_stage = [&](int c) {
        const int k0 = c << 5;
        const uint32_t st = sb + (uint32_t)(c % 3) * G1_STAGE;
        const h16* s0 = arr ? (B + (size_t)(n0 + lrow) * ldb + k0)
                            : (A + (size_t)(m0 + lrow) * lda + k0);
        const uint32_t b0 = st + (uint32_t)arr * G_TILE;
#pragma unroll
        for (int kc = 0; kc < 4; kc++)
            cp16(b0 + tile_off(lrow, kc), s0 + kc * 8);
        cp_commit();
    };

    load_stage(0);
    if (NC > 1) load_stage(1);

    const int lrow16 = lane & 15;
    const int lhi    = lane >> 4;

    for (int c = 0; c < NC; c++) {
        if (c + 1 < NC) cp_wait<1>();
        else            cp_wait<0>();
        __syncthreads();

        const uint32_t st = sb + (uint32_t)(c % 3) * G1_STAGE;

#pragma unroll
        for (int kb2 = 0; kb2 < 2; kb2++) {
            const int kcb = kb2 * 2;
            uint32_t af[2][4];
#pragma unroll
            for (int mt = 0; mt < 2; mt++)
                ldm_x4(af[mt], st + tile_off(wm + mt * 16 + lrow16, kcb + lhi));
#pragma unroll
            for (int g = 0; g < 4; g++) {
                uint32_t bf[4];
                ldm_x4(bf, st + G_TILE + tile_off(wn + g * 16 + lrow16, kcb + lhi));
#pragma unroll
                for (int mt = 0; mt < 2; mt++) {
#pragma unroll
                    for (int sub = 0; sub < 2; sub++)
                        mma_f32(accf[mt][g * 2 + sub], af[mt], bf[sub], bf[sub + 2]);
                }
            }
        }
        if (c + 2 < NC) load_stage(c + 2);
    }

#pragma unroll
    for (int mt = 0; mt < 2; mt++) {
        const int mrow = m0 + wm + mt * 16 + (lane >> 2);
#pragma unroll
        for (int g = 0; g < 4; g++) {
#pragma unroll
            for (int sub = 0; sub < 2; sub++) {
                const float* d = accf[mt][g * 2 + sub];
                const int n = n0 + wn + g * 16 + sub * 8 + (lane & 3) * 2;
                *(float2*)(C + (size_t)mrow * ldc + n) =
                    make_float2(d[0] * alpha, d[1] * alpha);
                *(float2*)(C + (size_t)(mrow + 8) * ldc + n) =
                    make_float2(d[2] * alpha, d[3] * alpha);
            }
        }
    }
}

// ---------------------------------------------------------------------------
// Launch
// ---------------------------------------------------------------------------
extern "C" void kernel_launch(void* const* d_in, const int* in_sizes, int n_in,
                              void* d_out, int out_size)
{
    (void)in_sizes; (void)n_in; (void)out_size;
    const float* x    = (const float*)d_in[0];
    const void*  wq   = d_in[1];
    const float* sq   = (const float*)d_in[2];
    const void*  wk   = d_in[3];
    const float* sk   = (const float*)d_in[4];
    const void*  wv   = d_in[5];
    const float* sv   = (const float*)d_in[6];
    const void*  wo   = d_in[7];
    const float* so   = (const float*)d_in[8];
    const float* cosb = (const float*)d_in[9];
    const float* sinb = (const float*)d_in[10];
    float* out = (float*)d_out;

    float *xq, *xk, *xv, *sc, *att;
    h16 *xh, *xl, *qh, *ql, *kh, *kl, *vth, *ath, *ph;
    h16 *nibq, *nibk, *nibv, *nibo;
    int8_t *wq8, *wk8, *wv8, *wo8;

    cudaGetSymbolAddress((void**)&xq,  g_xq);
    cudaGetSymbolAddress((void**)&xk,  g_xk);
    cudaGetSymbolAddress((void**)&xv,  g_xv);
    cudaGetSymbolAddress((void**)&sc,  g_sc);
    cudaGetSymbolAddress((void**)&att, g_att);
    cudaGetSymbolAddress((void**)&xh,  g_xh);   cudaGetSymbolAddress((void**)&xl,  g_xl);
    cudaGetSymbolAddress((void**)&qh,  g_qh);   cudaGetSymbolAddress((void**)&ql,  g_ql);
    cudaGetSymbolAddress((void**)&kh,  g_kh);   cudaGetSymbolAddress((void**)&kl,  g_kl);
    cudaGetSymbolAddress((void**)&vth, g_vth);
    cudaGetSymbolAddress((void**)&ath, g_ath);
    cudaGetSymbolAddress((void**)&ph,  g_ph);
    cudaGetSymbolAddress((void**)&nibq, g_nibq); cudaGetSymbolAddress((void**)&nibk, g_nibk);
    cudaGetSymbolAddress((void**)&nibv, g_nibv); cudaGetSymbolAddress((void**)&nibo, g_nibo);
    cudaGetSymbolAddress((void**)&wq8, g_wq8);  cudaGetSymbolAddress((void**)&wk8, g_wk8);
    cudaGetSymbolAddress((void**)&wv8, g_wv8);  cudaGetSymbolAddress((void**)&wo8, g_wo8);

    cudaFuncSetAttribute(gemm_w4<1>, cudaFuncAttributeMaxDynamicSharedMemorySize, W4_SMEM);
    cudaFuncSetAttribute(gemm_w4<0>, cudaFuncAttributeMaxDynamicSharedMemorySize, W4_SMEM);
    cudaFuncSetAttribute(gemm3, cudaFuncAttributeMaxDynamicSharedMemorySize, G3_SMEM);
    cudaFuncSetAttribute(gemm1, cudaFuncAttributeMaxDynamicSharedMemorySize, G1_SMEM);

    const dim3 blk(256);
    const long nq = (long)DM * DM / 2;
    const long nk = (long)KVD * DM / 2;

    // ingest q-path first; launch #6 = gemm_w4 q-proj (ncu window)
    probe_mode<<<1, 32>>>((const int*)wq);                                 // 1
    repack_w<<<1024, blk>>>(wq, wq8, nq);                                  // 2
    unpack_nib_h<<<2048, blk>>>(wq8, nibq, (long)DM * DM);                 // 3
    split_f32<<<2048, blk>>>(x, xh, xl, (long)SEQ * DM);                   // 4
    repack_w<<<1024, blk>>>(wk, wk8, nk);                                  // 5
    gemm_w4<1><<<dim3(DM / 128, SEQ / 128), blk, W4_SMEM>>>(               // 6 (ncu)
        xh, xl, nibq, sq, xq, DM, DM);

    repack_w<<<1024, blk>>>(wv, wv8, nk);
    repack_w<<<1024, blk>>>(wo, wo8, nq);
    unpack_nib_h<<<2048, blk>>>(wk8, nibk, (long)KVD * DM);
    unpack_nib_h<<<2048, blk>>>(wv8, nibv, (long)KVD * DM);
    unpack_nib_h<<<2048, blk>>>(wo8, nibo, (long)DM * DM);

    // k-proj (2-term exact), v-proj (1-term, exact weights)
    gemm_w4<1><<<dim3(KVD / 128, SEQ / 128), blk, W4_SMEM>>>(
        xh, xl, nibk, sk, xk, DM, KVD);
    gemm_w4<0><<<dim3(KVD / 128, SEQ / 128), blk, W4_SMEM>>>(
        xh, xh, nibv, sv, xv, DM, KVD);

    // RoPE (+1/sqrt(HD) on q) -> fp16 splits; V transpose
    rope_split<<<(SEQ * NH  * 64 + 255) / 256, blk>>>(xq, cosb, sinb, qh, ql, NH,
                                                      0.08838834764831843f);
    rope_split<<<(SEQ * NKV * 64 + 255) / 256, blk>>>(xk, cosb, sinb, kh, kl, NKV, 1.0f);
    vtrans_h<<<(NKV * HD * SEQ + 255) / 256, blk>>>(xv, vth);

    // scores = (q/sqrt(HD)) K^T  (fp16 3-term, lower-triangular tiles)
    gemm3<<<dim3(SEQ / 128, SEQ / 128, NH), blk, G3_SMEM>>>(
        qh, ql, kh, kl, sc, HD, DM, KVD, SEQ,
        (long)HD, (long)HD, NH / NKV, (long)SEQ * SEQ, 1.0f, 1);

    // causal softmax -> fp16 probs
    softmax_h<<<NH * SEQ, 128>>>(sc, ph);

    // att = P V  (fp16 1-term, k-limited)
    gemm1<<<dim3(HD / 128, SEQ / 128, NH), blk, G1_SMEM>>>(
        ph, vth, att, SEQ, SEQ, SEQ, DM,
        (long)SEQ * SEQ, (long)HD * SEQ, NH / NKV, (long)HD, 1.0f, 2);

    // output projection (1-term, exact weights)
    cvt_f32h<<<2048, blk>>>(att, ath, (long)SEQ * DM);
    gemm_w4<0><<<dim3(DM / 128, SEQ / 128), blk, W4_SMEM>>>(
        ath, ath, nibo, so, out, DM, DM);
}

// round 9
// speedup vs baseline: 1.5484x; 1.0446x over previous
#include <cuda_runtime.h>
#include <cuda_fp16.h>
#include <cstdint>

// ---------------------------------------------------------------------------
// Problem constants
// ---------------------------------------------------------------------------
#define SEQ   2048
#define DM    4096
#define NH    32
#define NKV   8
#define HD    128
#define KVD   (NKV * HD)   // 1024

typedef __half h16;

// ---------------------------------------------------------------------------
// Device-global scratch (allocation-free rule)
// ---------------------------------------------------------------------------
__device__ float g_xq[SEQ * DM];
__device__ float g_xk[SEQ * KVD];
__device__ float g_xv[SEQ * KVD];
__device__ float g_sc[(size_t)NH * SEQ * SEQ];     // fp32 scores

// fp16 operands
__device__ __align__(16) h16 g_xh [SEQ * DM],  g_xl [SEQ * DM];  // x split
__device__ __align__(16) h16 g_qh [SEQ * DM],  g_ql [SEQ * DM];  // q split (QK)
__device__ __align__(16) h16 g_kh [SEQ * KVD], g_kl [SEQ * KVD]; // k split (QK)
__device__ __align__(16) h16 g_vth[NKV * HD * SEQ];              // V^T plain
__device__ __align__(16) h16 g_ath[SEQ * DM];                    // att plain (PV out)
__device__ __align__(16) h16 g_ph [(size_t)NH * SEQ * SEQ];      // probs plain

// exact fp16 nibble planes (weight = nib * group_scale)
__device__ __align__(16) h16 g_nibq[DM * DM];
__device__ __align__(16) h16 g_nibk[KVD * DM];
__device__ __align__(16) h16 g_nibv[KVD * DM];
__device__ __align__(16) h16 g_nibo[DM * DM];

__device__ int g_mode;

// ---------------------------------------------------------------------------
// PTX helpers (base sm_103 ISA: cp.async / ldmatrix / mma.sync)
// ---------------------------------------------------------------------------
__device__ __forceinline__ uint32_t smem_u32(const void* p) {
    uint32_t a;
    asm("{ .reg .u64 t; cvta.to.shared.u64 t, %1; cvt.u32.u64 %0, t; }" : "=r"(a) : "l"(p));
    return a;
}
__device__ __forceinline__ void cp16(uint32_t dst, const void* src) {
    asm volatile("cp.async.cg.shared.global [%0], [%1], 16;" :: "r"(dst), "l"(src) : "memory");
}
__device__ __forceinline__ void cp4(uint32_t dst, const void* src) {
    asm volatile("cp.async.ca.shared.global [%0], [%1], 4;" :: "r"(dst), "l"(src) : "memory");
}
__device__ __forceinline__ void cp_commit() {
    asm volatile("cp.async.commit_group;" ::: "memory");
}
template <int N>
__device__ __forceinline__ void cp_wait() {
    asm volatile("cp.async.wait_group %0;" :: "n"(N) : "memory");
}
__device__ __forceinline__ void ldm_x4(uint32_t* r, uint32_t addr) {
    asm volatile("ldmatrix.sync.aligned.m8n8.x4.shared.b16 {%0,%1,%2,%3}, [%4];"
                 : "=r"(r[0]), "=r"(r[1]), "=r"(r[2]), "=r"(r[3]) : "r"(addr));
}
__device__ __forceinline__ void mma_f32(float* d, const uint32_t* a,
                                        uint32_t b0, uint32_t b1) {
    asm volatile(
        "mma.sync.aligned.m16n8k16.row.col.f32.f16.f16.f32 "
        "{%0,%1,%2,%3}, {%4,%5,%6,%7}, {%8,%9}, {%0,%1,%2,%3};"
        : "+f"(d[0]), "+f"(d[1]), "+f"(d[2]), "+f"(d[3])
        : "r"(a[0]), "r"(a[1]), "r"(a[2]), "r"(a[3]), "r"(b0), "r"(b1));
}
__device__ __forceinline__ void mma_f16(uint32_t* d, const uint32_t* a,
                                        uint32_t b0, uint32_t b1) {
    asm volatile(
        "mma.sync.aligned.m16n8k16.row.col.f16.f16.f16.f16 "
        "{%0,%1}, {%2,%3,%4,%5}, {%6,%7}, {%0,%1};"
        : "+r"(d[0]), "+r"(d[1])
        : "r"(a[0]), "r"(a[1]), "r"(a[2]), "r"(a[3]), "r"(b0), "r"(b1));
}

// Permuted conflict-free smem layouts: atom = 8 rows x 16B, 128B blocks.
__device__ __forceinline__ uint32_t tile_off(int row, int kc) {     // 32-wide fp16 tile
    return (uint32_t)((((row >> 3) * 4 + kc) << 7) + ((row & 7) << 4));
}
__device__ __forceinline__ uint32_t off8(int row, int kc) {         // 64-wide fp16 tile
    return (uint32_t)((((row >> 3) * 8 + kc) << 7) + ((row & 7) << 4));
}

// ---------------------------------------------------------------------------
// Probe (dtype-robust weight ingestion)
// ---------------------------------------------------------------------------
__global__ void probe_mode(const int* __restrict__ w)
{
    if (threadIdx.x == 0 && blockIdx.x == 0) {
        int ok = 0;
        for (int i = 0; i < 256; i++) {
            const int v = w[i];
            if (v >= -128 && v <= 127) ok++;
        }
        g_mode = (ok >= 250) ? 1 : 0;
    }
}

// Unpack Q4_0 nibbles directly from the raw input (mode-aware) to fp16 planes.
__global__ __launch_bounds__(256) void unpack_nib_h(
    const void* __restrict__ in, h16* __restrict__ nib, long n)
{
    const int mode = g_mode;
    const long stride = (long)gridDim.x * blockDim.x;
    for (long f = (long)blockIdx.x * blockDim.x + threadIdx.x; f < n; f += stride) {
        const int  q = (int)(f & 127);
        const long b = (f >> 7) * 64 + (q & 63);
        const int8_t raw = mode ? (int8_t)((const int*)in)[b]
                                : ((const int8_t*)in)[b];
        const int v = (q < 64) ? (raw >> 4) : (((int8_t)(raw << 4)) >> 4);
        nib[f] = __float2half((float)v);
    }
}

// fp32 -> fp16 hi/lo split
__global__ __launch_bounds__(256) void split_f32(
    const float* __restrict__ src, h16* __restrict__ hi, h16* __restrict__ lo, long n)
{
    const long stride = (long)gridDim.x * blockDim.x;
    for (long i = (long)blockIdx.x * blockDim.x + threadIdx.x; i < n; i += stride) {
        const float v = src[i];
        const h16 h = __float2half(v);
        hi[i] = h;
        lo[i] = __float2half(v - __half2float(h));
    }
}

// ---------------------------------------------------------------------------
// RoPE (rotate-half) + optional scale + fp16 split.  x laid out [S, nh, HD].
// ---------------------------------------------------------------------------
__global__ __launch_bounds__(256) void rope_split(
    const float* __restrict__ x, const float* __restrict__ cosb,
    const float* __restrict__ sinb, h16* __restrict__ oh, h16* __restrict__ ol,
    int nheads, float scale)
{
    const long total = (long)SEQ * nheads * 64;
    long idx = (long)blockIdx.x * blockDim.x + threadIdx.x;
    if (idx >= total) return;
    const int d = (int)(idx & 63);
    const int h = (int)((idx >> 6) % nheads);
    const int s = (int)(idx / ((long)64 * nheads));
    const size_t base = (size_t)s * nheads * HD + h * HD + d;
    const float c  = cosb[s * 64 + d];
    const float sn = sinb[s * 64 + d];
    const float lo = x[base];
    const float hi = x[base + 64];
    const float r0 = (lo * c - hi * sn) * scale;
    const float r1 = (hi * c + lo * sn) * scale;
    h16 h0 = __float2half(r0);
    h16 h1 = __float2half(r1);
    oh[base]      = h0;
    ol[base]      = __float2half(r0 - __half2float(h0));
    oh[base + 64] = h1;
    ol[base + 64] = __float2half(r1 - __half2float(h1));
}

// ---------------------------------------------------------------------------
// Transpose V to plain fp16: vt[kv][d][s] = xv[s][kv*HD + d]
// ---------------------------------------------------------------------------
__global__ __launch_bounds__(256) void vtrans_h(
    const float* __restrict__ xv, h16* __restrict__ vt)
{
    const long total = (long)NKV * HD * SEQ;
    long idx = (long)blockIdx.x * blockDim.x + threadIdx.x;
    if (idx >= total) return;
    const int s  = (int)(idx % SEQ);
    const int d  = (int)((idx / SEQ) % HD);
    const int kv = (int)(idx / ((long)SEQ * HD));
    vt[idx] = __float2half(xv[(size_t)s * KVD + kv * HD + d]);
}

// ---------------------------------------------------------------------------
// Causal row softmax, smem-resident (single global read).
// fp32 scores -> plain fp16 probs, zero-filled to next 128 boundary.
// ---------------------------------------------------------------------------
__global__ __launch_bounds__(256) void softmax_h(
    const float* __restrict__ sc, h16* __restrict__ ph)
{
    __shared__ float srow[SEQ];
    __shared__ float red[8];
    const int row = blockIdx.x;          // h*SEQ + q
    const int q   = row & (SEQ - 1);
    const float* p = sc + (size_t)row * SEQ;
    h16* oh = ph + (size_t)row * SEQ;
    const int len  = q + 1;
    const int zend = ((q >> 7) + 1) << 7;
    const int tid  = threadIdx.x;

    float m = -1e30f;
    for (int k = tid; k < len; k += 256) {
        const float v = p[k];
        srow[k] = v;
        m = fmaxf(m, v);
    }
#pragma unroll
    for (int o = 16; o > 0; o >>= 1) m = fmaxf(m, __shfl_xor_sync(0xffffffffu, m, o));
    if ((tid & 31) == 0) red[tid >> 5] = m;
    __syncthreads();
    m = red[0];
#pragma unroll
    for (int i = 1; i < 8; i++) m = fmaxf(m, red[i]);
    __syncthreads();

    float sum = 0.0f;
    for (int k = tid; k < len; k += 256) {
        const float e = __expf(srow[k] - m);
        srow[k] = e;
        sum += e;
    }
#pragma unroll
    for (int o = 16; o > 0; o >>= 1) sum += __shfl_xor_sync(0xffffffffu, sum, o);
    if ((tid & 31) == 0) red[tid >> 5] = sum;
    __syncthreads();
    sum = red[0];
#pragma unroll
    for (int i = 1; i < 8; i++) sum += red[i];

    const float inv = 1.0f / sum;
    for (int k = tid; k < len; k += 256)
        oh[k] = __float2half(srow[k] * inv);
    const h16 z = __float2half(0.0f);
    for (int k = len + tid; k < zend; k += 256) oh[k] = z;
}

// ---------------------------------------------------------------------------
// GEMM_W4: projection GEMM, exact fp16 nibble weights + fp32 group scales.
// 512 threads, 16 warps in 4x4 grid, warp tile 32x32, CTA 128x128, BK=64,
// 3-stage cp.async.  TWO=1: Ah+Al activation terms; TWO=0: Ah only.
// ---------------------------------------------------------------------------
#define W4_TILE 16384                        // 128 x 64 fp16

template <int TWO>
__global__ __launch_bounds__(512, 1) void gemm_w4(
    const h16* __restrict__ Ah, const h16* __restrict__ Al,
    const h16* __restrict__ Nib, const float* __restrict__ Sc,
    float* __restrict__ C, int K, int ldc)
{
    constexpr int NT    = TWO ? 3 : 2;
    constexpr int STAGE = NT * W4_TILE;

    const int m0 = blockIdx.y * 128;
    const int n0 = blockIdx.x * 128;

    extern __shared__ char smem[];
    const uint32_t sb  = smem_u32(smem);
    const uint32_t ssc = sb + 3 * STAGE;
    const int tid  = threadIdx.x;
    const int wid  = tid >> 5;
    const int lane = tid & 31;

    const int NC = K >> 6;
    const int KG = K >> 6;

    const int wm = (wid & 3) * 32;
    const int wn = (wid >> 2) * 32;

    float accf[2][4][4];
#pragma unroll
    for (int i = 0; i < 2; i++)
#pragma unroll
        for (int j = 0; j < 4; j++)
#pragma unroll
            for (int v = 0; v < 4; v++) accf[i][j][v] = 0.0f;

    auto load_stage = [&](int c) {
        const int k0 = c << 6;
        const uint32_t st = sb + (uint32_t)(c % 3) * STAGE;
        const int total = NT << 10;                 // NT tiles * 128 rows * 8 chunks
        for (int i = tid; i < total; i += 512) {
            const int tile = i >> 10;
            const int row  = (i >> 3) & 127;
            const int kc   = i & 7;
            const h16* src;
            uint32_t dstb;
            if (tile == 0)             { src = Ah  + (size_t)(m0 + row) * K + k0; dstb = st; }
            else if (TWO && tile == 1) { src = Al  + (size_t)(m0 + row) * K + k0; dstb = st + W4_TILE; }
            else                       { src = Nib + (size_t)(n0 + row) * K + k0; dstb = st + (NT - 1) * W4_TILE; }
            cp16(dstb + off8(row, kc), src + kc * 8);
        }
        if (tid < 128)
            cp4(ssc + (uint32_t)(c % 3) * 512 + tid * 4,
                Sc + (size_t)(n0 + tid) * KG + c);
        cp_commit();
    };

    load_stage(0);
    if (NC > 1) load_stage(1);

    const int lrow16 = lane & 15;
    const int lhi    = lane >> 4;

    for (int c = 0; c < NC; c++) {
        if (c + 1 < NC) cp_wait<1>();
        else            cp_wait<0>();
        __syncthreads();

        const uint32_t st = sb + (uint32_t)(c % 3) * STAGE;
        const float* ss = (const float*)(smem + 3 * STAGE + (c % 3) * 512);

        float accg[2][4][4];
#pragma unroll
        for (int i = 0; i < 2; i++)
#pragma unroll
            for (int j = 0; j < 4; j++)
#pragma unroll
                for (int v = 0; v < 4; v++) accg[i][j][v] = 0.0f;

#pragma unroll
        for (int kb = 0; kb < 4; kb++) {
            uint32_t afh[2][4], afl[2][4];
#pragma unroll
            for (int mt = 0; mt < 2; mt++) {
                const uint32_t off = off8(wm + mt * 16 + lrow16, kb * 2 + lhi);
                ldm_x4(afh[mt], st + off);
                if (TWO) ldm_x4(afl[mt], st + W4_TILE + off);
            }
#pragma unroll
            for (int g = 0; g < 2; g++) {
                uint32_t bf[4];
                ldm_x4(bf, st + (NT - 1) * W4_TILE +
                           off8(wn + g * 16 + lrow16, kb * 2 + lhi));
#pragma unroll
                for (int mt = 0; mt < 2; mt++) {
#pragma unroll
                    for (int sub = 0; sub < 2; sub++) {
                        mma_f32(accg[mt][g * 2 + sub], afh[mt], bf[sub], bf[sub + 2]);
                        if (TWO)
                            mma_f32(accg[mt][g * 2 + sub], afl[mt], bf[sub], bf[sub + 2]);
                    }
                }
            }
        }

        // drain group acc with per-n scale
#pragma unroll
        for (int g = 0; g < 2; g++)
#pragma unroll
            for (int sub = 0; sub < 2; sub++) {
                const int nn = wn + g * 16 + sub * 8 + (lane & 3) * 2;
                const float s0 = ss[nn];
                const float s1 = ss[nn + 1];
#pragma unroll
                for (int mt = 0; mt < 2; mt++) {
                    float* f = accf[mt][g * 2 + sub];
                    const float* a = accg[mt][g * 2 + sub];
                    f[0] += a[0] * s0;
                    f[1] += a[1] * s1;
                    f[2] += a[2] * s0;
                    f[3] += a[3] * s1;
                }
            }

        if (c + 2 < NC) load_stage(c + 2);
    }

#pragma unroll
    for (int mt = 0; mt < 2; mt++) {
        const int mrow = m0 + wm + mt * 16 + (lane >> 2);
#pragma unroll
        for (int g = 0; g < 2; g++)
#pragma unroll
            for (int sub = 0; sub < 2; sub++) {
                const float* d = accf[mt][g * 2 + sub];
                const int n = n0 + wn + g * 16 + sub * 8 + (lane & 3) * 2;
                *(float2*)(C + (size_t)mrow * ldc + n)       = make_float2(d[0], d[1]);
                *(float2*)(C + (size_t)(mrow + 8) * ldc + n) = make_float2(d[2], d[3]);
            }
    }
}

// ---------------------------------------------------------------------------
// GEMM3: QK^T fp16 split GEMM (3 terms; cross terms in f16 acc).
// 512 threads, 16 warps 4x4, warp tile 32x32, CTA 128x128, BK=32, 3-stage.
// causal==1: skip tile if n0 > m0+127.
// ---------------------------------------------------------------------------
#define G_TILE 8192
#define G3_STAGE (4 * G_TILE)
#define G3_SMEM  (3 * G3_STAGE)
#define G1_STAGE (2 * G_TILE)
#define G1_SMEM  (3 * G1_STAGE)

__global__ __launch_bounds__(512, 1) void gemm3(
    const h16* __restrict__ Ah, const h16* __restrict__ Al,
    const h16* __restrict__ Bh, const h16* __restrict__ Bl,
    float* __restrict__ Cb,
    int K, int lda, int ldb, int ldc,
    long a_hs, long b_hs, int b_div, long c_hs,
    float alpha, int causal)
{
    const int m0 = blockIdx.y * 128;
    const int n0 = blockIdx.x * 128;
    if (causal == 1 && n0 > m0 + 127) return;

    extern __shared__ char smem[];
    const uint32_t sb = smem_u32(smem);
    const int tid  = threadIdx.x;
    const int wid  = tid >> 5;
    const int lane = tid & 31;
    const int h = blockIdx.z;

    const h16* ah = Ah + (long)h * a_hs;
    const h16* al = Al + (long)h * a_hs;
    const h16* bh = Bh + (long)(h / b_div) * b_hs;
    const h16* bl = Bl + (long)(h / b_div) * b_hs;
    float* C = Cb + (long)h * c_hs;

    const int NC = K >> 5;
    const int wm = (wid & 3) * 32;
    const int wn = (wid >> 2) * 32;

    float    accf[2][4][4];
    uint32_t accc[2][4][2];
#pragma unroll
    for (int i = 0; i < 2; i++)
#pragma unroll
        for (int j = 0; j < 4; j++) {
#pragma unroll
            for (int v = 0; v < 4; v++) accf[i][j][v] = 0.0f;
            accc[i][j][0] = 0u; accc[i][j][1] = 0u;
        }

    const int lrow = tid & 127;
    const int quarter = tid >> 7;    // 0:Ah 1:Al 2:Bh 3:Bl
    auto load_stage = [&](int c) {
        const int k0 = c << 5;
        const uint32_t st = sb + (uint32_t)(c % 3) * G3_STAGE;
        const h16* s0;
        if      (quarter == 0) s0 = ah + (size_t)(m0 + lrow) * lda + k0;
        else if (quarter == 1) s0 = al + (size_t)(m0 + lrow) * lda + k0;
        else if (quarter == 2) s0 = bh + (size_t)(n0 + lrow) * ldb + k0;
        else                   s0 = bl + (size_t)(n0 + lrow) * ldb + k0;
        const uint32_t b0 = st + (uint32_t)quarter * G_TILE;
#pragma unroll
        for (int kc = 0; kc < 4; kc++)
            cp16(b0 + tile_off(lrow, kc), s0 + kc * 8);
        cp_commit();
    };

    load_stage(0);
    if (NC > 1) load_stage(1);

    const int lrow16 = lane & 15;
    const int lhi    = lane >> 4;

    for (int c = 0; c < NC; c++) {
        if (c + 1 < NC) cp_wait<1>();
        else            cp_wait<0>();
        __syncthreads();

        const uint32_t st = sb + (uint32_t)(c % 3) * G3_STAGE;

#pragma unroll
        for (int kb2 = 0; kb2 < 2; kb2++) {
            const int kcb = kb2 * 2;
            uint32_t afh[2][4], afl[2][4];
#pragma unroll
            for (int mt = 0; mt < 2; mt++) {
                const uint32_t off = tile_off(wm + mt * 16 + lrow16, kcb + lhi);
                ldm_x4(afh[mt], st + 0 * G_TILE + off);
                ldm_x4(afl[mt], st + 1 * G_TILE + off);
            }
#pragma unroll
            for (int g = 0; g < 2; g++) {
                const uint32_t boff = tile_off(wn + g * 16 + lrow16, kcb + lhi);
                uint32_t bhf[4], blf[4];
                ldm_x4(bhf, st + 2 * G_TILE + boff);
                ldm_x4(blf, st + 3 * G_TILE + boff);
#pragma unroll
                for (int mt = 0; mt < 2; mt++) {
#pragma unroll
                    for (int sub = 0; sub < 2; sub++) {
                        mma_f32(accf[mt][g * 2 + sub], afh[mt], bhf[sub], bhf[sub + 2]);
                        mma_f16(accc[mt][g * 2 + sub], afh[mt], blf[sub], blf[sub + 2]);
                        mma_f16(accc[mt][g * 2 + sub], afl[mt], bhf[sub], bhf[sub + 2]);
                    }
                }
            }
        }
        if (c + 2 < NC) load_stage(c + 2);
    }

#pragma unroll
    for (int mt = 0; mt < 2; mt++) {
        const int mrow = m0 + wm + mt * 16 + (lane >> 2);
#pragma unroll
        for (int g = 0; g < 2; g++) {
#pragma unroll
            for (int sub = 0; sub < 2; sub++) {
                const float* d = accf[mt][g * 2 + sub];
                const __half2 c0 = *(const __half2*)&accc[mt][g * 2 + sub][0];
                const __half2 c1 = *(const __half2*)&accc[mt][g * 2 + sub][1];
                const int n = n0 + wn + g * 16 + sub * 8 + (lane & 3) * 2;
                *(float2*)(C + (size_t)mrow * ldc + n) =
                    make_float2((d[0] + __low2float(c0)) * alpha,
                                (d[1] + __high2float(c0)) * alpha);
                *(float2*)(C + (size_t)(mrow + 8) * ldc + n) =
                    make_float2((d[2] + __low2float(c1)) * alpha,
                                (d[3] + __high2float(c1)) * alpha);
            }
        }
    }
}

// ---------------------------------------------------------------------------
// GEMM1: PV plain fp16 GEMM, fp32 acc, optional fp16 output.
// 256 threads, launch_bounds(256,2) -> 2 CTAs/SM (4 warps/SMSP).
// causal==2: K <= m0+128.
// ---------------------------------------------------------------------------
template <int HOUT>
__global__ __launch_bounds__(256, 2) void gemm1(
    const h16* __restrict__ Ab, const h16* __restrict__ Bb,
    void* __restrict__ Cb,
    int K, int lda, int ldb, int ldc,
    long a_hs, long b_hs, int b_div, long c_hs,
    float alpha, int causal)
{
    const int m0 = blockIdx.y * 128;
    const int n0 = blockIdx.x * 128;

    extern __shared__ char smem[];
    const uint32_t sb = smem_u32(smem);
    const int tid  = threadIdx.x;
    const int wid  = tid >> 5;
    const int lane = tid & 31;
    const int h = blockIdx.z;

    const h16* A = Ab + (long)h * a_hs;
    const h16* B = Bb + (long)(h / b_div) * b_hs;

    const int kmax = (causal == 2) ? min(K, m0 + 128) : K;
    const int NC = kmax >> 5;

    const int wm = (wid & 3) * 32;
    const int wn = (wid >> 2) * 64;

    float accf[2][8][4];
#pragma unroll
    for (int i = 0; i < 2; i++)
#pragma unroll
        for (int j = 0; j < 8; j++)
#pragma unroll
            for (int v = 0; v < 4; v++) accf[i][j][v] = 0.0f;

    const int lrow = tid & 127;
    const int arr  = tid >> 7;
    auto load_stage = [&](int c) {
        const int k0 = c << 5;
        const uint32_t st = sb + (uint32_t)(c % 3) * G1_STAGE;
        const h16* s0 = arr ? (B + (size_t)(n0 + lrow) * ldb + k0)
                            : (A + (size_t)(m0 + lrow) * lda + k0);
        const uint32_t b0 = st + (uint32_t)arr * G_TILE;
#pragma unroll
        for (int kc = 0; kc < 4; kc++)
            cp16(b0 + tile_off(lrow, kc), s0 + kc * 8);
        cp_commit();
    };

    load_stage(0);
    if (NC > 1) load_stage(1);

    const int lrow16 = lane & 15;
    const int lhi    = lane >> 4;

    for (int c = 0; c < NC; c++) {
        if (c + 1 < NC) cp_wait<1>();
        else            cp_wait<0>();
        __syncthreads();

        const uint32_t st = sb + (uint32_t)(c % 3) * G1_STAGE;

#pragma unroll
        for (int kb2 = 0; kb2 < 2; kb2++) {
            const int kcb = kb2 * 2;
            uint32_t af[2][4];
#pragma unroll
            for (int mt = 0; mt < 2; mt++)
                ldm_x4(af[mt], st + tile_off(wm + mt * 16 + lrow16, kcb + lhi));
#pragma unroll
            for (int g = 0; g < 4; g++) {
                uint32_t bf[4];
                ldm_x4(bf, st + G_TILE + tile_off(wn + g * 16 + lrow16, kcb + lhi));
#pragma unroll
                for (int mt = 0; mt < 2; mt++) {
#pragma unroll
                    for (int sub = 0; sub < 2; sub++)
                        mma_f32(accf[mt][g * 2 + sub], af[mt], bf[sub], bf[sub + 2]);
                }
            }
        }
        if (c + 2 < NC) load_stage(c + 2);
    }

#pragma unroll
    for (int mt = 0; mt < 2; mt++) {
        const int mrow = m0 + wm + mt * 16 + (lane >> 2);
#pragma unroll
        for (int g = 0; g < 4; g++) {
#pragma unroll
            for (int sub = 0; sub < 2; sub++) {
                const float* d = accf[mt][g * 2 + sub];
                const int n = n0 + wn + g * 16 + sub * 8 + (lane & 3) * 2;
                if (HOUT) {
                    h16* C = (h16*)Cb + (long)h * c_hs;
                    *(__half2*)(C + (size_t)mrow * ldc + n) =
                        __floats2half2_rn(d[0] * alpha, d[1] * alpha);
                    *(__half2*)(C + (size_t)(mrow + 8) * ldc + n) =
                        __floats2half2_rn(d[2] * alpha, d[3] * alpha);
                } else {
                    float* C = (float*)Cb + (long)h * c_hs;
                    *(float2*)(C + (size_t)mrow * ldc + n) =
                        make_float2(d[0] * alpha, d[1] * alpha);
                    *(float2*)(C + (size_t)(mrow + 8) * ldc + n) =
                        make_float2(d[2] * alpha, d[3] * alpha);
                }
            }
        }
    }
}

// ---------------------------------------------------------------------------
// Launch
// ---------------------------------------------------------------------------
extern "C" void kernel_launch(void* const* d_in, const int* in_sizes, int n_in,
                              void* d_out, int out_size)
{
    (void)in_sizes; (void)n_in; (void)out_size;
    const float* x    = (const float*)d_in[0];
    const void*  wq   = d_in[1];
    const float* sq   = (const float*)d_in[2];
    const void*  wk   = d_in[3];
    const float* sk   = (const float*)d_in[4];
    const void*  wv   = d_in[5];
    const float* sv   = (const float*)d_in[6];
    const void*  wo   = d_in[7];
    const float* so   = (const float*)d_in[8];
    const float* cosb = (const float*)d_in[9];
    const float* sinb = (const float*)d_in[10];
    float* out = (float*)d_out;

    float *xq, *xk, *xv, *sc;
    h16 *xh, *xl, *qh, *ql, *kh, *kl, *vth, *ath, *ph;
    h16 *nibq, *nibk, *nibv, *nibo;

    cudaGetSymbolAddress((void**)&xq,  g_xq);
    cudaGetSymbolAddress((void**)&xk,  g_xk);
    cudaGetSymbolAddress((void**)&xv,  g_xv);
    cudaGetSymbolAddress((void**)&sc,  g_sc);
    cudaGetSymbolAddress((void**)&xh,  g_xh);   cudaGetSymbolAddress((void**)&xl,  g_xl);
    cudaGetSymbolAddress((void**)&qh,  g_qh);   cudaGetSymbolAddress((void**)&ql,  g_ql);
    cudaGetSymbolAddress((void**)&kh,  g_kh);   cudaGetSymbolAddress((void**)&kl,  g_kl);
    cudaGetSymbolAddress((void**)&vth, g_vth);
    cudaGetSymbolAddress((void**)&ath, g_ath);
    cudaGetSymbolAddress((void**)&ph,  g_ph);
    cudaGetSymbolAddress((void**)&nibq, g_nibq); cudaGetSymbolAddress((void**)&nibk, g_nibk);
    cudaGetSymbolAddress((void**)&nibv, g_nibv); cudaGetSymbolAddress((void**)&nibo, g_nibo);

    const int W4S2 = 3 * (2 * W4_TILE) + 3 * 512;   // TWO=0
    const int W4S3 = 3 * (3 * W4_TILE) + 3 * 512;   // TWO=1
    cudaFuncSetAttribute(gemm_w4<1>, cudaFuncAttributeMaxDynamicSharedMemorySize, W4S3);
    cudaFuncSetAttribute(gemm_w4<0>, cudaFuncAttributeMaxDynamicSharedMemorySize, W4S2);
    cudaFuncSetAttribute(gemm3, cudaFuncAttributeMaxDynamicSharedMemorySize, G3_SMEM);
    cudaFuncSetAttribute(gemm1<0>, cudaFuncAttributeMaxDynamicSharedMemorySize, G1_SMEM);
    cudaFuncSetAttribute(gemm1<1>, cudaFuncAttributeMaxDynamicSharedMemorySize, G1_SMEM);

    const dim3 blk(256);
    const dim3 blkG(512);

    // ingest; launch #6 = gemm_w4 q-proj (ncu window)
    probe_mode<<<1, 32>>>((const int*)wq);                                 // 1
    unpack_nib_h<<<2048, blk>>>(wq, nibq, (long)DM * DM);                  // 2
    split_f32<<<2048, blk>>>(x, xh, xl, (long)SEQ * DM);                   // 3
    unpack_nib_h<<<2048, blk>>>(wk, nibk, (long)KVD * DM);                 // 4
    unpack_nib_h<<<2048, blk>>>(wv, nibv, (long)KVD * DM);                 // 5
    gemm_w4<1><<<dim3(DM / 128, SEQ / 128), blkG, W4S3>>>(                 // 6 (ncu)
        xh, xl, nibq, sq, xq, DM, DM);

    unpack_nib_h<<<2048, blk>>>(wo, nibo, (long)DM * DM);

    // k-proj (2-term exact), v-proj (1-term, exact weights)
    gemm_w4<1><<<dim3(KVD / 128, SEQ / 128), blkG, W4S3>>>(
        xh, xl, nibk, sk, xk, DM, KVD);
    gemm_w4<0><<<dim3(KVD / 128, SEQ / 128), blkG, W4S2>>>(
        xh, xh, nibv, sv, xv, DM, KVD);

    // RoPE (+1/sqrt(HD) on q) -> fp16 splits; V transpose
    rope_split<<<(SEQ * NH  * 64 + 255) / 256, blk>>>(xq, cosb, sinb, qh, ql, NH,
                                                      0.08838834764831843f);
    rope_split<<<(SEQ * NKV * 64 + 255) / 256, blk>>>(xk, cosb, sinb, kh, kl, NKV, 1.0f);
    vtrans_h<<<(NKV * HD * SEQ + 255) / 256, blk>>>(xv, vth);

    // scores = (q/sqrt(HD)) K^T  (fp16 3-term, lower-triangular tiles)
    gemm3<<<dim3(SEQ / 128, SEQ / 128, NH), blkG, G3_SMEM>>>(
        qh, ql, kh, kl, sc, HD, DM, KVD, SEQ,
        (long)HD, (long)HD, NH / NKV, (long)SEQ * SEQ, 1.0f, 1);

    // causal softmax -> fp16 probs (smem-resident)
    softmax_h<<<NH * SEQ, blk>>>(sc, ph);

    // att = P V  (fp16 1-term, k-limited) -> fp16 directly
    gemm1<1><<<dim3(HD / 128, SEQ / 128, NH), blk, G1_SMEM>>>(
        ph, vth, ath, SEQ, SEQ, SEQ, DM,
        (long)SEQ * SEQ, (long)HD * SEQ, NH / NKV, (long)HD, 1.0f, 2);

    // output projection (1-term, exact weights)
    gemm_w4<0><<<dim3(DM / 128, SEQ / 128), blkG, W4S2>>>(
        ath, ath, nibo, so, out, DM, DM);
}

// round 11
// speedup vs baseline: 1.7838x; 1.1520x over previous
#include <cuda_runtime.h>
#include <cuda_fp16.h>
#include <cstdint>
#include <cstring>

// ---------------------------------------------------------------------------
// Problem constants
// ---------------------------------------------------------------------------
#define SEQ   2048
#define DM    4096
#define NH    32
#define NKV   8
#define HD    128
#define KVD   (NKV * HD)   // 1024

typedef __half h16;

// ---------------------------------------------------------------------------
// Device-global scratch (allocation-free rule)
// ---------------------------------------------------------------------------
__device__ float g_xq[SEQ * DM];
__device__ float g_xk[SEQ * KVD];
__device__ float g_xv[SEQ * KVD];

__device__ __align__(16) h16 g_xh [SEQ * DM],  g_xl [SEQ * DM];  // x split
__device__ __align__(16) h16 g_qh [SEQ * DM],  g_ql [SEQ * DM];  // q split
__device__ __align__(16) h16 g_kh [SEQ * KVD], g_kl [SEQ * KVD]; // k split
__device__ __align__(16) h16 g_vth[NKV * HD * SEQ];              // V^T plain
__device__ __align__(16) h16 g_ath[SEQ * DM];                    // attention out

// exact fp16 nibble planes (weight = nib * group_scale)
__device__ __align__(16) h16 g_nibq[DM * DM];
__device__ __align__(16) h16 g_nibk[KVD * DM];
__device__ __align__(16) h16 g_nibv[KVD * DM];
__device__ __align__(16) h16 g_nibo[DM * DM];

__device__ int g_mode;

// ---------------------------------------------------------------------------
// PTX helpers (base sm_103 ISA: cp.async / ldmatrix / mma.sync)
// ---------------------------------------------------------------------------
__device__ __forceinline__ uint32_t smem_u32(const void* p) {
    uint32_t a;
    asm("{ .reg .u64 t; cvta.to.shared.u64 t, %1; cvt.u32.u64 %0, t; }" : "=r"(a) : "l"(p));
    return a;
}
__device__ __forceinline__ void cp16(uint32_t dst, const void* src) {
    asm volatile("cp.async.cg.shared.global [%0], [%1], 16;" :: "r"(dst), "l"(src) : "memory");
}
__device__ __forceinline__ void cp4(uint32_t dst, const void* src) {
    asm volatile("cp.async.ca.shared.global [%0], [%1], 4;" :: "r"(dst), "l"(src) : "memory");
}
__device__ __forceinline__ void cp_commit() {
    asm volatile("cp.async.commit_group;" ::: "memory");
}
template <int N>
__device__ __forceinline__ void cp_wait() {
    asm volatile("cp.async.wait_group %0;" :: "n"(N) : "memory");
}
__device__ __forceinline__ void ldm_x4(uint32_t* r, uint32_t addr) {
    asm volatile("ldmatrix.sync.aligned.m8n8.x4.shared.b16 {%0,%1,%2,%3}, [%4];"
                 : "=r"(r[0]), "=r"(r[1]), "=r"(r[2]), "=r"(r[3]) : "r"(addr));
}
__device__ __forceinline__ void mma_f32(float* d, const uint32_t* a,
                                        uint32_t b0, uint32_t b1) {
    asm volatile(
        "mma.sync.aligned.m16n8k16.row.col.f32.f16.f16.f32 "
        "{%0,%1,%2,%3}, {%4,%5,%6,%7}, {%8,%9}, {%0,%1,%2,%3};"
        : "+f"(d[0]), "+f"(d[1]), "+f"(d[2]), "+f"(d[3])
        : "r"(a[0]), "r"(a[1]), "r"(a[2]), "r"(a[3]), "r"(b0), "r"(b1));
}
__device__ __forceinline__ void mma_f16(uint32_t* d, const uint32_t* a,
                                        uint32_t b0, uint32_t b1) {
    asm volatile(
        "mma.sync.aligned.m16n8k16.row.col.f16.f16.f16.f16 "
        "{%0,%1}, {%2,%3,%4,%5}, {%6,%7}, {%0,%1};"
        : "+r"(d[0]), "+r"(d[1])
        : "r"(a[0]), "r"(a[1]), "r"(a[2]), "r"(a[3]), "r"(b0), "r"(b1));
}

// Pack two floats into one uint32 holding an fp16 pair (BOTH halves).
__device__ __forceinline__ uint32_t pack_h2(float a, float b) {
    __half2 t = __floats2half2_rn(a, b);
    uint32_t r;
    memcpy(&r, &t, 4);
    return r;
}

// Permuted conflict-free smem layouts: atom = 8 rows x 16B, 128B blocks.
__device__ __forceinline__ uint32_t off8(int row, int kc) {   // 64-wide fp16 tile
    return (uint32_t)((((row >> 3) * 8 + kc) << 7) + ((row & 7) << 4));
}
__device__ __forceinline__ uint32_t off16(int row, int kc) {  // 128-wide fp16 tile
    return (uint32_t)((((row >> 3) * 16 + kc) << 7) + ((row & 7) << 4));
}

// ---------------------------------------------------------------------------
// Probe (dtype-robust weight ingestion)
// ---------------------------------------------------------------------------
__global__ void probe_mode(const int* __restrict__ w)
{
    if (threadIdx.x == 0 && blockIdx.x == 0) {
        int ok = 0;
        for (int i = 0; i < 256; i++) {
            const int v = w[i];
            if (v >= -128 && v <= 127) ok++;
        }
        g_mode = (ok >= 250) ? 1 : 0;
    }
}

// Unpack Q4_0 nibbles directly from raw input (mode-aware) to fp16 planes.
__global__ __launch_bounds__(256) void unpack_nib_h(
    const void* __restrict__ in, h16* __restrict__ nib, long n)
{
    const int mode = g_mode;
    const long stride = (long)gridDim.x * blockDim.x;
    for (long f = (long)blockIdx.x * blockDim.x + threadIdx.x; f < n; f += stride) {
        const int  q = (int)(f & 127);
        const long b = (f >> 7) * 64 + (q & 63);
        const int8_t raw = mode ? (int8_t)((const int*)in)[b]
                                : ((const int8_t*)in)[b];
        const int v = (q < 64) ? (raw >> 4) : (((int8_t)(raw << 4)) >> 4);
        nib[f] = __float2half((float)v);
    }
}

// fp32 -> fp16 hi/lo split
__global__ __launch_bounds__(256) void split_f32(
    const float* __restrict__ src, h16* __restrict__ hi, h16* __restrict__ lo, long n)
{
    const long stride = (long)gridDim.x * blockDim.x;
    for (long i = (long)blockIdx.x * blockDim.x + threadIdx.x; i < n; i += stride) {
        const float v = src[i];
        const h16 h = __float2half(v);
        hi[i] = h;
        lo[i] = __float2half(v - __half2float(h));
    }
}

// ---------------------------------------------------------------------------
// RoPE (rotate-half) + optional scale + fp16 split.  x laid out [S, nh, HD].
// ---------------------------------------------------------------------------
__global__ __launch_bounds__(256) void rope_split(
    const float* __restrict__ x, const float* __restrict__ cosb,
    const float* __restrict__ sinb, h16* __restrict__ oh, h16* __restrict__ ol,
    int nheads, float scale)
{
    const long total = (long)SEQ * nheads * 64;
    long idx = (long)blockIdx.x * blockDim.x + threadIdx.x;
    if (idx >= total) return;
    const int d = (int)(idx & 63);
    const int h = (int)((idx >> 6) % nheads);
    const int s = (int)(idx / ((long)64 * nheads));
    const size_t base = (size_t)s * nheads * HD + h * HD + d;
    const float c  = cosb[s * 64 + d];
    const float sn = sinb[s * 64 + d];
    const float lo = x[base];
    const float hi = x[base + 64];
    const float r0 = (lo * c - hi * sn) * scale;
    const float r1 = (hi * c + lo * sn) * scale;
    h16 h0 = __float2half(r0);
    h16 h1 = __float2half(r1);
    oh[base]      = h0;
    ol[base]      = __float2half(r0 - __half2float(h0));
    oh[base + 64] = h1;
    ol[base + 64] = __float2half(r1 - __half2float(h1));
}

// ---------------------------------------------------------------------------
// Transpose V to plain fp16: vt[kv][d][s] = xv[s][kv*HD + d]
// ---------------------------------------------------------------------------
__global__ __launch_bounds__(256) void vtrans_h(
    const float* __restrict__ xv, h16* __restrict__ vt)
{
    const long total = (long)NKV * HD * SEQ;
    long idx = (long)blockIdx.x * blockDim.x + threadIdx.x;
    if (idx >= total) return;
    const int s  = (int)(idx % SEQ);
    const int d  = (int)((idx / SEQ) % HD);
    const int kv = (int)(idx / ((long)SEQ * HD));
    vt[idx] = __float2half(xv[(size_t)s * KVD + kv * HD + d]);
}

// ---------------------------------------------------------------------------
// GEMM_W4: projection GEMM, exact fp16 nibble weights + fp32 group scales.
// 512 threads, 16 warps 4x4, warp 32x32, CTA 128x128, BK=64, 3-stage.
// ---------------------------------------------------------------------------
#define W4_TILE 16384

template <int TWO>
__global__ __launch_bounds__(512, 1) void gemm_w4(
    const h16* __restrict__ Ah, const h16* __restrict__ Al,
    const h16* __restrict__ Nib, const float* __restrict__ Sc,
    float* __restrict__ C, int K, int ldc)
{
    constexpr int NT    = TWO ? 3 : 2;
    constexpr int STAGE = NT * W4_TILE;

    const int m0 = blockIdx.y * 128;
    const int n0 = blockIdx.x * 128;

    extern __shared__ char smem[];
    const uint32_t sb  = smem_u32(smem);
    const uint32_t ssc = sb + 3 * STAGE;
    const int tid  = threadIdx.x;
    const int wid  = tid >> 5;
    const int lane = tid & 31;

    const int NC = K >> 6;
    const int KG = K >> 6;

    const int wm = (wid & 3) * 32;
    const int wn = (wid >> 2) * 32;

    float accf[2][4][4];
#pragma unroll
    for (int i = 0; i < 2; i++)
#pragma unroll
        for (int j = 0; j < 4; j++)
#pragma unroll
            for (int v = 0; v < 4; v++) accf[i][j][v] = 0.0f;

    auto load_stage = [&](int c) {
        const int k0 = c << 6;
        const uint32_t st = sb + (uint32_t)(c % 3) * STAGE;
        const int total = NT << 10;
        for (int i = tid; i < total; i += 512) {
            const int tile = i >> 10;
            const int row  = (i >> 3) & 127;
            const int kc   = i & 7;
            const h16* src;
            uint32_t dstb;
            if (tile == 0)             { src = Ah  + (size_t)(m0 + row) * K + k0; dstb = st; }
            else if (TWO && tile == 1) { src = Al  + (size_t)(m0 + row) * K + k0; dstb = st + W4_TILE; }
            else                       { src = Nib + (size_t)(n0 + row) * K + k0; dstb = st + (NT - 1) * W4_TILE; }
            cp16(dstb + off8(row, kc), src + kc * 8);
        }
        if (tid < 128)
            cp4(ssc + (uint32_t)(c % 3) * 512 + tid * 4,
                Sc + (size_t)(n0 + tid) * KG + c);
        cp_commit();
    };

    load_stage(0);
    if (NC > 1) load_stage(1);

    const int lrow16 = lane & 15;
    const int lhi    = lane >> 4;

    for (int c = 0; c < NC; c++) {
        if (c + 1 < NC) cp_wait<1>();
        else            cp_wait<0>();
        __syncthreads();

        const uint32_t st = sb + (uint32_t)(c % 3) * STAGE;
        const float* ss = (const float*)(smem + 3 * STAGE + (c % 3) * 512);

        float accg[2][4][4];
#pragma unroll
        for (int i = 0; i < 2; i++)
#pragma unroll
            for (int j = 0; j < 4; j++)
#pragma unroll
                for (int v = 0; v < 4; v++) accg[i][j][v] = 0.0f;

#pragma unroll
        for (int kb = 0; kb < 4; kb++) {
            uint32_t afh[2][4], afl[2][4];
#pragma unroll
            for (int mt = 0; mt < 2; mt++) {
                const uint32_t off = off8(wm + mt * 16 + lrow16, kb * 2 + lhi);
                ldm_x4(afh[mt], st + off);
                if (TWO) ldm_x4(afl[mt], st + W4_TILE + off);
            }
#pragma unroll
            for (int g = 0; g < 2; g++) {
                uint32_t bf[4];
                ldm_x4(bf, st + (NT - 1) * W4_TILE +
                           off8(wn + g * 16 + lrow16, kb * 2 + lhi));
#pragma unroll
                for (int mt = 0; mt < 2; mt++) {
#pragma unroll
                    for (int sub = 0; sub < 2; sub++) {
                        mma_f32(accg[mt][g * 2 + sub], afh[mt], bf[sub], bf[sub + 2]);
                        if (TWO)
                            mma_f32(accg[mt][g * 2 + sub], afl[mt], bf[sub], bf[sub + 2]);
                    }
                }
            }
        }

#pragma unroll
        for (int g = 0; g < 2; g++)
#pragma unroll
            for (int sub = 0; sub < 2; sub++) {
                const int nn = wn + g * 16 + sub * 8 + (lane & 3) * 2;
                const float s0 = ss[nn];
                const float s1 = ss[nn + 1];
#pragma unroll
                for (int mt = 0; mt < 2; mt++) {
                    float* f = accf[mt][g * 2 + sub];
                    const float* a = accg[mt][g * 2 + sub];
                    f[0] += a[0] * s0;
                    f[1] += a[1] * s1;
                    f[2] += a[2] * s0;
                    f[3] += a[3] * s1;
                }
            }

        if (c + 2 < NC) load_stage(c + 2);
    }

#pragma unroll
    for (int mt = 0; mt < 2; mt++) {
        const int mrow = m0 + wm + mt * 16 + (lane >> 2);
#pragma unroll
        for (int g = 0; g < 2; g++)
#pragma unroll
            for (int sub = 0; sub < 2; sub++) {
                const float* d = accf[mt][g * 2 + sub];
                const int n = n0 + wn + g * 16 + sub * 8 + (lane & 3) * 2;
                *(float2*)(C + (size_t)mrow * ldc + n)       = make_float2(d[0], d[1]);
                *(float2*)(C + (size_t)(mrow + 8) * ldc + n) = make_float2(d[2], d[3]);
            }
    }
}

// ---------------------------------------------------------------------------
// Fused flash attention: S = Q K^T (3-term split) -> online softmax -> O = P V.
// Grid (NH, 16 q-tiles, heavy first). 256 threads, 8 warps; warp = 16 q-rows
// x full 128-key tile.  Smem: Qh|Ql persistent, K single buffer, V double.
// Output fp16 [s][h*HD+d].
// ---------------------------------------------------------------------------
#define FA_QH 0
#define FA_QL 32768
#define FA_KH 65536
#define FA_KL 98304
#define FA_V0 131072
#define FA_V1 163840
#define FA_SMEM 196608

__global__ __launch_bounds__(256, 1) void flash_attn(
    const h16* __restrict__ Qh, const h16* __restrict__ Ql,
    const h16* __restrict__ Kh, const h16* __restrict__ Kl,
    const h16* __restrict__ Vt, h16* __restrict__ O)
{
    extern __shared__ char smem[];
    const uint32_t sb = smem_u32(smem);
    const int h   = blockIdx.x;
    const int qt  = gridDim.y - 1 - blockIdx.y;   // heavy tiles first
    const int kvh = h / (NH / NKV);
    const int tid = threadIdx.x;
    const int wid = tid >> 5;
    const int lane = tid & 31;
    const int NT = qt + 1;

    // ---- prologue loads: Q (group), K0 (group), V0 (group) ----
    for (int i = tid; i < 2048; i += 256) {
        const int row = i >> 4, c = i & 15;
        const size_t g = (size_t)(qt * 128 + row) * DM + h * HD + c * 8;
        cp16(sb + FA_QH + off16(row, c), Qh + g);
        cp16(sb + FA_QL + off16(row, c), Ql + g);
    }
    cp_commit();
    for (int i = tid; i < 2048; i += 256) {
        const int row = i >> 4, c = i & 15;
        const size_t g = (size_t)row * KVD + kvh * HD + c * 8;
        cp16(sb + FA_KH + off16(row, c), Kh + g);
        cp16(sb + FA_KL + off16(row, c), Kl + g);
    }
    cp_commit();
    for (int i = tid; i < 2048; i += 256) {
        const int row = i >> 4, c = i & 15;
        cp16(sb + FA_V0 + off16(row, c), Vt + (size_t)(kvh * HD + row) * SEQ + c * 8);
    }
    cp_commit();
    cp_wait<1>();            // Q + K0 complete (V0 may be in flight)
    __syncthreads();

    const int g8     = lane >> 2;
    const int qd     = lane & 3;
    const int lrow16 = lane & 15;
    const int lhi    = lane >> 4;
    const int wq     = wid * 16;

    float of[16][4];
#pragma unroll
    for (int j = 0; j < 16; j++)
#pragma unroll
        for (int v = 0; v < 4; v++) of[j][v] = 0.0f;
    float m0 = -1e30f, m1 = -1e30f, l0 = 0.0f, l1 = 0.0f;

    for (int kt = 0; kt < NT; kt++) {
        // ---- S = Q K^T (3-term) ----
        float    accf[16][4];
        uint32_t accc[16][2];
#pragma unroll
        for (int j = 0; j < 16; j++) {
#pragma unroll
            for (int v = 0; v < 4; v++) accf[j][v] = 0.0f;
            accc[j][0] = 0u; accc[j][1] = 0u;
        }

#pragma unroll
        for (int kb = 0; kb < 8; kb++) {       // k16 chunks over d=128
            uint32_t aqh[4], aql[4];
            const uint32_t aoff = off16(wq + lrow16, kb * 2 + lhi);
            ldm_x4(aqh, sb + FA_QH + aoff);
            ldm_x4(aql, sb + FA_QL + aoff);
#pragma unroll
            for (int g = 0; g < 8; g++) {      // n16 groups over 128 keys
                const uint32_t boff = off16(g * 16 + lrow16, kb * 2 + lhi);
                uint32_t bkh[4], bkl[4];
                ldm_x4(bkh, sb + FA_KH + boff);
                ldm_x4(bkl, sb + FA_KL + boff);
#pragma unroll
                for (int sub = 0; sub < 2; sub++) {
                    mma_f32(accf[g * 2 + sub], aqh, bkh[sub], bkh[sub + 2]);
                    mma_f16(accc[g * 2 + sub], aqh, bkl[sub], bkl[sub + 2]);
                    mma_f16(accc[g * 2 + sub], aql, bkh[sub], bkh[sub + 2]);
                }
            }
        }
        // combine cross terms
#pragma unroll
        for (int j = 0; j < 16; j++) {
            const __half2 c0 = *(const __half2*)&accc[j][0];
            const __half2 c1 = *(const __half2*)&accc[j][1];
            accf[j][0] += __low2float(c0);
            accf[j][1] += __high2float(c0);
            accf[j][2] += __low2float(c1);
            accf[j][3] += __high2float(c1);
        }
        // causal mask on diagonal tile
        if (kt == qt) {
            const int r0 = wq + g8, r1 = r0 + 8;
#pragma unroll
            for (int j = 0; j < 16; j++) {
                const int cb = j * 8 + qd * 2;
                if (cb     > r0) accf[j][0] = -1e30f;
                if (cb + 1 > r0) accf[j][1] = -1e30f;
                if (cb     > r1) accf[j][2] = -1e30f;
                if (cb + 1 > r1) accf[j][3] = -1e30f;
            }
        }
        // ---- online softmax ----
        float mx0 = -1e30f, mx1 = -1e30f;
#pragma unroll
        for (int j = 0; j < 16; j++) {
            mx0 = fmaxf(mx0, fmaxf(accf[j][0], accf[j][1]));
            mx1 = fmaxf(mx1, fmaxf(accf[j][2], accf[j][3]));
        }
        mx0 = fmaxf(mx0, __shfl_xor_sync(0xffffffffu, mx0, 1));
        mx0 = fmaxf(mx0, __shfl_xor_sync(0xffffffffu, mx0, 2));
        mx1 = fmaxf(mx1, __shfl_xor_sync(0xffffffffu, mx1, 1));
        mx1 = fmaxf(mx1, __shfl_xor_sync(0xffffffffu, mx1, 2));

        const float nm0 = fmaxf(m0, mx0);
        const float nm1 = fmaxf(m1, mx1);
        const float sc0 = __expf(m0 - nm0);
        const float sc1 = __expf(m1 - nm1);
        float sum0 = 0.0f, sum1 = 0.0f;
#pragma unroll
        for (int j = 0; j < 16; j++) {
            accf[j][0] = __expf(accf[j][0] - nm0);
            accf[j][1] = __expf(accf[j][1] - nm0);
            accf[j][2] = __expf(accf[j][2] - nm1);
            accf[j][3] = __expf(accf[j][3] - nm1);
            sum0 += accf[j][0] + accf[j][1];
            sum1 += accf[j][2] + accf[j][3];
        }
        sum0 += __shfl_xor_sync(0xffffffffu, sum0, 1);
        sum0 += __shfl_xor_sync(0xffffffffu, sum0, 2);
        sum1 += __shfl_xor_sync(0xffffffffu, sum1, 1);
        sum1 += __shfl_xor_sync(0xffffffffu, sum1, 2);
        l0 = l0 * sc0 + sum0;
        l1 = l1 * sc1 + sum1;
        m0 = nm0;
        m1 = nm1;
#pragma unroll
        for (int j = 0; j < 16; j++) {
            of[j][0] *= sc0; of[j][1] *= sc0;
            of[j][2] *= sc1; of[j][3] *= sc1;
        }

        __syncthreads();     // all warps done reading K smem

        const uint32_t vb = (kt & 1) ? FA_V1 : FA_V0;
        if (kt + 1 < NT) {
            const int kt1 = kt + 1;
            for (int i = tid; i < 2048; i += 256) {
                const int row = i >> 4, c = i & 15;
                const size_t g = (size_t)(kt1 * 128 + row) * KVD + kvh * HD + c * 8;
                cp16(sb + FA_KH + off16(row, c), Kh + g);
                cp16(sb + FA_KL + off16(row, c), Kl + g);
            }
            cp_commit();
            const uint32_t vb1 = (kt1 & 1) ? FA_V1 : FA_V0;
            for (int i = tid; i < 2048; i += 256) {
                const int row = i >> 4, c = i & 15;
                cp16(sb + vb1 + off16(row, c),
                     Vt + (size_t)(kvh * HD + row) * SEQ + kt1 * 128 + c * 8);
            }
            cp_commit();
            cp_wait<2>();    // V[kt] complete (K[kt+1], V[kt+1] in flight)
        } else {
            cp_wait<0>();
        }
        __syncthreads();

        // ---- O += P V ----
#pragma unroll
        for (int c = 0; c < 8; c++) {          // k16 chunks over keys
            uint32_t pa[4];
            pa[0] = pack_h2(accf[2 * c][0],     accf[2 * c][1]);
            pa[1] = pack_h2(accf[2 * c][2],     accf[2 * c][3]);
            pa[2] = pack_h2(accf[2 * c + 1][0], accf[2 * c + 1][1]);
            pa[3] = pack_h2(accf[2 * c + 1][2], accf[2 * c + 1][3]);
#pragma unroll
            for (int gn = 0; gn < 8; gn++) {   // n16 groups over d=128
                uint32_t bf[4];
                ldm_x4(bf, sb + vb + off16(gn * 16 + lrow16, c * 2 + lhi));
                mma_f32(of[gn * 2 + 0], pa, bf[0], bf[2]);
                mma_f32(of[gn * 2 + 1], pa, bf[1], bf[3]);
            }
        }

        if (kt + 1 < NT) { cp_wait<1>(); __syncthreads(); }  // K[kt+1] ready
    }

    // ---- epilogue: normalize and write fp16 ----
    const float inv0 = 1.0f / l0;
    const float inv1 = 1.0f / l1;
    const int s0 = qt * 128 + wq + g8;
#pragma unroll
    for (int j = 0; j < 16; j++) {
        const int d = h * HD + j * 8 + qd * 2;
        *(__half2*)(O + (size_t)s0 * DM + d) =
            __floats2half2_rn(of[j][0] * inv0, of[j][1] * inv0);
        *(__half2*)(O + (size_t)(s0 + 8) * DM + d) =
            __floats2half2_rn(of[j][2] * inv1, of[j][3] * inv1);
    }
}

// ---------------------------------------------------------------------------
// Launch
// ---------------------------------------------------------------------------
extern "C" void kernel_launch(void* const* d_in, const int* in_sizes, int n_in,
                              void* d_out, int out_size)
{
    (void)in_sizes; (void)n_in; (void)out_size;
    const float* x    = (const float*)d_in[0];
    const void*  wq   = d_in[1];
    const float* sq   = (const float*)d_in[2];
    const void*  wk   = d_in[3];
    const float* sk   = (const float*)d_in[4];
    const void*  wv   = d_in[5];
    const float* sv   = (const float*)d_in[6];
    const void*  wo   = d_in[7];
    const float* so   = (const float*)d_in[8];
    const float* cosb = (const float*)d_in[9];
    const float* sinb = (const float*)d_in[10];
    float* out = (float*)d_out;

    float *xq, *xk, *xv;
    h16 *xh, *xl, *qh, *ql, *kh, *kl, *vth, *ath;
    h16 *nibq, *nibk, *nibv, *nibo;

    cudaGetSymbolAddress((void**)&xq,  g_xq);
    cudaGetSymbolAddress((void**)&xk,  g_xk);
    cudaGetSymbolAddress((void**)&xv,  g_xv);
    cudaGetSymbolAddress((void**)&xh,  g_xh);   cudaGetSymbolAddress((void**)&xl,  g_xl);
    cudaGetSymbolAddress((void**)&qh,  g_qh);   cudaGetSymbolAddress((void**)&ql,  g_ql);
    cudaGetSymbolAddress((void**)&kh,  g_kh);   cudaGetSymbolAddress((void**)&kl,  g_kl);
    cudaGetSymbolAddress((void**)&vth, g_vth);
    cudaGetSymbolAddress((void**)&ath, g_ath);
    cudaGetSymbolAddress((void**)&nibq, g_nibq); cudaGetSymbolAddress((void**)&nibk, g_nibk);
    cudaGetSymbolAddress((void**)&nibv, g_nibv); cudaGetSymbolAddress((void**)&nibo, g_nibo);

    const int W4S2 = 3 * (2 * W4_TILE) + 3 * 512;
    const int W4S3 = 3 * (3 * W4_TILE) + 3 * 512;
    cudaFuncSetAttribute(gemm_w4<1>, cudaFuncAttributeMaxDynamicSharedMemorySize, W4S3);
    cudaFuncSetAttribute(gemm_w4<0>, cudaFuncAttributeMaxDynamicSharedMemorySize, W4S2);
    cudaFuncSetAttribute(flash_attn, cudaFuncAttributeMaxDynamicSharedMemorySize, FA_SMEM);

    const dim3 blk(256);
    const dim3 blkG(512);

    // ingest; launch #6 = gemm_w4 q-proj (ncu window)
    probe_mode<<<1, 32>>>((const int*)wq);                                 // 1
    unpack_nib_h<<<2048, blk>>>(wq, nibq, (long)DM * DM);                  // 2
    split_f32<<<2048, blk>>>(x, xh, xl, (long)SEQ * DM);                   // 3
    unpack_nib_h<<<2048, blk>>>(wk, nibk, (long)KVD * DM);                 // 4
    unpack_nib_h<<<2048, blk>>>(wv, nibv, (long)KVD * DM);                 // 5
    gemm_w4<1><<<dim3(DM / 128, SEQ / 128), blkG, W4S3>>>(                 // 6 (ncu)
        xh, xl, nibq, sq, xq, DM, DM);

    unpack_nib_h<<<2048, blk>>>(wo, nibo, (long)DM * DM);

    gemm_w4<1><<<dim3(KVD / 128, SEQ / 128), blkG, W4S3>>>(
        xh, xl, nibk, sk, xk, DM, KVD);
    gemm_w4<0><<<dim3(KVD / 128, SEQ / 128), blkG, W4S2>>>(
        xh, xh, nibv, sv, xv, DM, KVD);

    rope_split<<<(SEQ * NH  * 64 + 255) / 256, blk>>>(xq, cosb, sinb, qh, ql, NH,
                                                      0.08838834764831843f);
    rope_split<<<(SEQ * NKV * 64 + 255) / 256, blk>>>(xk, cosb, sinb, kh, kl, NKV, 1.0f);
    vtrans_h<<<(NKV * HD * SEQ + 255) / 256, blk>>>(xv, vth);

    // fused attention: QK^T (3-term) + online softmax + PV -> fp16 att
    flash_attn<<<dim3(NH, SEQ / 128), blk, FA_SMEM>>>(qh, ql, kh, kl, vth, ath);

    // output projection (1-term, exact weights)
    gemm_w4<0><<<dim3(DM / 128, SEQ / 128), blkG, W4S2>>>(
        ath, ath, nibo, so, out, DM, DM);
}